// round 15
// baseline (speedup 1.0000x reference)
#include <cuda_runtime.h>
#include <math.h>

#define NN 256
#define SS 64
#define WWIN 256
#define HH 32

// ---------------- scratch ------------------------------------------------------
__device__ float g_WhF[NN*SS*WWIN];
__device__ float g_WhT[NN*WWIN*SS];
__device__ float g_Tat[NN*WWIN*SS];
__device__ float g_Fat[NN*SS*WWIN];
__device__ float g_gi[NN*SS*96];
__device__ float g_gru[NN*SS*HH];
__device__ float g_ct[NN*SS];
__device__ float g_cat2[NN*2*SS];
__device__ float g_F[4*NN*WWIN];       // F1F | F2F | F1T | F2T

#define FMA_F32X2(d, a, b, c) \
    asm("fma.rn.f32x2 %0, %1, %2, %3;" : "=l"(d) : "l"(a), "l"(b), "l"(c))
#define PACK_F32X2(out, lo, hi) \
    asm("mov.b64 %0, {%1, %2};" : "=l"(out) : "r"(lo), "r"(hi))
#define UNPACK_F32X2(lo, hi, in) \
    asm("mov.b64 {%0, %1}, %2;" : "=r"(lo), "=r"(hi) : "l"(in))

// ---------------- gemm_wh impl (device) ----------------------------------------
template<int BM, int BN>
__device__ __forceinline__ void gemm_wh_impl(
    float* smem, int b, int bx, int by,
    const float* __restrict__ A, const float* __restrict__ B,
    float* __restrict__ C,
    int M, int N, int K,
    long long sAb, int sAm, int sAk,
    long long sBb, int sBk, int sBn,
    long long sCb, int sCm,
    const float* __restrict__ avec, long long aStride,
    float* __restrict__ F1o, float* __restrict__ F2o)
{
    constexpr int TX = BN / 8;
    constexpr int LA = BM * 16 / 256;
    constexpr int LB = BN * 16 / 256;

    int m0 = by * BM;
    int n0 = bx * BN;
    const float* Ab = A + (size_t)b * sAb;
    const float* Bb = B + (size_t)b * sBb;
    float*       Cb = C + (size_t)b * sCb;

    float (*As)[BM] = (float(*)[BM])smem;
    float (*Bs)[BN] = (float(*)[BN])(smem + 16 * BM);

    int tid = threadIdx.x;
    int tx = tid % TX, ty = tid / TX;
    int r0  = ty * 4;
    int c0a = tx * 4;
    int c0b = BN / 2 + tx * 4;
    bool aK1 = (sAk == 1);

    unsigned long long acc2[2][8];
    #pragma unroll
    for (int p = 0; p < 2; p++)
        #pragma unroll
        for (int j = 0; j < 8; j++) acc2[p][j] = 0ull;

    auto loadA = [&](int k0, float r[LA]) {
        if (aK1) {
            #pragma unroll
            for (int l = 0; l < LA; l++) {
                int e = tid + l * 256; int m = e >> 4, kk = e & 15;
                r[l] = Ab[(size_t)(m0 + m) * sAm + (k0 + kk)];
            }
        } else {
            #pragma unroll
            for (int l = 0; l < LA; l++) {
                int e = tid + l * 256; int m = e % BM, kk = e / BM;
                r[l] = Ab[(size_t)(m0 + m) + (size_t)(k0 + kk) * sAk];
            }
        }
    };
    auto storeA = [&](float r[LA]) {
        if (aK1) {
            #pragma unroll
            for (int l = 0; l < LA; l++) { int e = tid + l * 256; As[e & 15][e >> 4] = r[l]; }
        } else {
            #pragma unroll
            for (int l = 0; l < LA; l++) { int e = tid + l * 256; As[e / BM][e % BM] = r[l]; }
        }
    };
    auto loadB = [&](int k0, float r[LB]) {
        #pragma unroll
        for (int l = 0; l < LB; l++) {
            int e = tid + l * 256; int n = e % BN, kk = e / BN; int gn = n0 + n;
            r[l] = Bb[(size_t)(k0 + kk) * sBk + (size_t)gn * sBn];
        }
    };
    auto storeB = [&](float r[LB]) {
        #pragma unroll
        for (int l = 0; l < LB; l++) { int e = tid + l * 256; Bs[e / BN][e % BN] = r[l]; }
    };

    float ra[LA], rb[LB], na[LA], nb[LB];
    loadA(0, ra); loadB(0, rb);

    for (int k0 = 0; k0 < K; k0 += 16) {
        storeA(ra); storeB(rb);
        __syncthreads();
        if (k0 + 16 < K) { loadA(k0 + 16, na); loadB(k0 + 16, nb); }
        #pragma unroll
        for (int kk = 0; kk < 16; kk++) {
            ulonglong2 a01 = *(const ulonglong2*)&As[kk][r0];
            unsigned long long a2[2] = {a01.x, a01.y};
            float4 bA = *(const float4*)&Bs[kk][c0a];
            float4 bB = *(const float4*)&Bs[kk][c0b];
            float bv[8] = {bA.x, bA.y, bA.z, bA.w, bB.x, bB.y, bB.z, bB.w};
            unsigned long long bd[8];
            #pragma unroll
            for (int j = 0; j < 8; j++) {
                unsigned int u = __float_as_uint(bv[j]);
                PACK_F32X2(bd[j], u, u);
            }
            #pragma unroll
            for (int p = 0; p < 2; p++)
                #pragma unroll
                for (int j = 0; j < 8; j++)
                    FMA_F32X2(acc2[p][j], a2[p], bd[j], acc2[p][j]);
        }
        __syncthreads();
        #pragma unroll
        for (int l = 0; l < LA; l++) ra[l] = na[l];
        #pragma unroll
        for (int l = 0; l < LB; l++) rb[l] = nb[l];
    }

    #pragma unroll
    for (int p = 0; p < 2; p++) {
        int gm0 = m0 + r0 + 2 * p;
        #pragma unroll
        for (int j = 0; j < 8; j++) {
            int gn = n0 + ((j < 4) ? (c0a + j) : (c0b + j - 4));
            unsigned int ul, uh;
            UNPACK_F32X2(ul, uh, acc2[p][j]);
            Cb[(size_t)gm0 * sCm + gn]       = __uint_as_float(ul);
            Cb[(size_t)(gm0 + 1) * sCm + gn] = __uint_as_float(uh);
        }
    }
    {
        const float* ab = avec + (size_t)b * aStride;
        float a1v[8], a2v[8];
        #pragma unroll
        for (int j = 0; j < 8; j++) {
            int gn = n0 + ((j < 4) ? (c0a + j) : (c0b + j - 4));
            a1v[j] = ab[gn];
            a2v[j] = ab[N + gn];
        }
        #pragma unroll
        for (int p = 0; p < 2; p++) {
            float s1l = 0.f, s1h = 0.f, s2l = 0.f, s2h = 0.f;
            #pragma unroll
            for (int j = 0; j < 8; j++) {
                unsigned int ul, uh;
                UNPACK_F32X2(ul, uh, acc2[p][j]);
                float v0 = __uint_as_float(ul), v1 = __uint_as_float(uh);
                s1l += v0 * a1v[j]; s1h += v1 * a1v[j];
                s2l += v0 * a2v[j]; s2h += v1 * a2v[j];
            }
            #pragma unroll
            for (int o = TX >> 1; o; o >>= 1) {
                s1l += __shfl_xor_sync(0xffffffffu, s1l, o);
                s1h += __shfl_xor_sync(0xffffffffu, s1h, o);
                s2l += __shfl_xor_sync(0xffffffffu, s2l, o);
                s2h += __shfl_xor_sync(0xffffffffu, s2h, o);
            }
            if (tx == 0) {
                int gm0 = m0 + r0 + 2 * p;
                atomicAdd(&F1o[(size_t)b * M + gm0],     s1l);
                atomicAdd(&F1o[(size_t)b * M + gm0 + 1], s1h);
                atomicAdd(&F2o[(size_t)b * M + gm0],     s2l);
                atomicAdd(&F2o[(size_t)b * M + gm0 + 1], s2h);
            }
        }
    }
}

__global__ void __launch_bounds__(256, 2) gemm_wh_both(
    const float* __restrict__ x,
    const float* __restrict__ FattW, const float* __restrict__ Fatta,
    const float* __restrict__ TattW, const float* __restrict__ Tatta,
    float* __restrict__ WhF, float* __restrict__ WhT,
    float* __restrict__ F1F, float* __restrict__ F2F,
    float* __restrict__ F1T, float* __restrict__ F2T)
{
    __shared__ float smem[16 * 64 + 16 * 128];
    if (blockIdx.z < 256) {
        if (blockIdx.y) return;
        gemm_wh_impl<64,128>(smem, blockIdx.z, blockIdx.x, 0,
            x, FattW, WhF, 64, 256, 256,
            16384LL, 256, 1,  65536LL, 256, 1,  16384LL, 256,
            Fatta, 512LL, F1F, F2F);
    } else {
        if (blockIdx.x) return;
        gemm_wh_impl<128,64>(smem, blockIdx.z - 256, 0, blockIdx.y,
            x, TattW, WhT, 256, 64, 64,
            16384LL, 1, 256,  4096LL, 64, 1,  16384LL, 64,
            Tatta, 128LL, F1T, F2T);
    }
}

// ---------------- gat_pv impl: wide tiles + double-buffered global loads --------
template<int BM, int BN, int RP, int CN>
__device__ __forceinline__ void gat_pv_impl(
    float* buf, int b, int bx, int by,
    const float* __restrict__ F1, const float* __restrict__ F2,
    const float* __restrict__ adj, long long adjBStride,
    const float* __restrict__ V, long long sVb, int sVm,
    int M,
    float* __restrict__ C, long long sCb, int sCm)
{
    constexpr int PS = BM + 8;
    constexpr int G  = 256 / BM;
    constexpr int KP = 32 / G;
    constexpr int TX = BN / CN;
    constexpr int LV = 32 * BN / 256;   // Bt elems / thread
    constexpr int LJ = BM * 32 / 256;   // adjS elems / thread
    int m0 = by * BM;
    int n0 = bx * BN;

    float* f1s  = buf;
    float* Ae   = buf + BM;
    float* Ape  = buf + 2 * BM;
    float* rsum = buf + 3 * BM;
    float* f2s  = buf + 4 * BM;
    float* Bks  = f2s + 32;
    float* Bkps = f2s + 64;
    float* rs   = f2s + 96;
    float* Pt   = rs + 256;
    float* Bt   = Pt + 32 * PS;
    float* adjS = Bt + 32 * BN;

    int tid = threadIdx.x;
    int tx = tid % TX, ty = tid / TX;
    int r0 = ty * 2 * RP, c0 = tx * CN;

    size_t base = (size_t)b * M;
    if (tid < BM) {
        float f = F1[base + m0 + tid];
        f1s[tid] = f;
        Ae[tid]  = __expf(f);
        Ape[tid] = __expf(0.2f * f);
        rsum[tid] = 0.f;
    }

    const float* adjb = adj + (size_t)b * adjBStride;
    const float* Vb   = V + (size_t)b * sVb;

    unsigned long long acc2[RP][CN];
    #pragma unroll
    for (int p = 0; p < RP; p++)
        #pragma unroll
        for (int j = 0; j < CN; j++) acc2[p][j] = 0ull;

    int mP = tid % BM;
    int kg = tid / BM;

    // register staging for next iteration
    float vReg[LV], aReg[LJ], f2v;

    auto loadTiles = [&](int k0) {
        #pragma unroll
        for (int l = 0; l < LV; l++) {
            int e = tid + l * 256;
            int n = e % BN, kk = e / BN;
            vReg[l] = Vb[(size_t)(k0 + kk) * sVm + n0 + n];
        }
        #pragma unroll
        for (int l = 0; l < LJ; l++) {
            int e = tid + l * 256;
            int m = e >> 5, kk = e & 31;
            aReg[l] = adjb[(size_t)(m0 + m) * M + k0 + kk];
        }
        if (tid < 32) f2v = F2[base + k0 + tid];
    };
    auto storeTiles = [&]() {
        #pragma unroll
        for (int l = 0; l < LV; l++) {
            int e = tid + l * 256;
            int n = e % BN, kk = e / BN;
            Bt[kk * BN + n] = vReg[l];
        }
        #pragma unroll
        for (int l = 0; l < LJ; l++) {
            int e = tid + l * 256;
            int m = e >> 5, kk = e & 31;
            adjS[m * 33 + kk] = aReg[l];
        }
        if (tid < 32) {
            f2s[tid]  = f2v;
            Bks[tid]  = __expf(f2v);
            Bkps[tid] = __expf(0.2f * f2v);
        }
    };

    loadTiles(0);

    for (int k0 = 0; k0 < M; k0 += 32) {
        __syncthreads();           // protect previous Pt/Bt/adjS reads
        storeTiles();
        __syncthreads();
        if (k0 + 32 < M) loadTiles(k0 + 32);   // overlap with compute below
        // P build
        float part = 0.f;
        {
            float f1m = f1s[mP], Em = Ae[mP], Epm = Ape[mP];
            #pragma unroll
            for (int l = 0; l < KP; l++) {
                int kk = kg * KP + l;
                float av = adjS[mP * 33 + kk];
                float f = f1m + f2s[kk];
                float p = (f >= 0.f) ? Em * Bks[kk] : Epm * Bkps[kk];
                p = (av > 0.f) ? p : 0.f;
                Pt[kk * PS + mP] = p;
                part += p;
            }
        }
        rs[tid] = part;
        __syncthreads();
        if (tid < BM) {
            float s = 0.f;
            #pragma unroll
            for (int g = 0; g < G; g++) s += rs[g * BM + tid];
            rsum[tid] += s;
        }
        #pragma unroll
        for (int kk = 0; kk < 32; kk++) {
            unsigned long long a2[RP];
            #pragma unroll
            for (int q = 0; q < RP / 2; q++) {
                ulonglong2 aa = *(const ulonglong2*)&Pt[kk * PS + r0 + q * 4];
                a2[2 * q] = aa.x; a2[2 * q + 1] = aa.y;
            }
            float bv[CN];
            #pragma unroll
            for (int q = 0; q < CN / 4; q++) {
                float4 b4 = *(const float4*)&Bt[kk * BN + c0 + q * 4];
                bv[4 * q] = b4.x; bv[4 * q + 1] = b4.y; bv[4 * q + 2] = b4.z; bv[4 * q + 3] = b4.w;
            }
            unsigned long long bd[CN];
            #pragma unroll
            for (int j = 0; j < CN; j++) {
                unsigned int u = __float_as_uint(bv[j]);
                PACK_F32X2(bd[j], u, u);
            }
            #pragma unroll
            for (int p = 0; p < RP; p++)
                #pragma unroll
                for (int j = 0; j < CN; j++)
                    FMA_F32X2(acc2[p][j], a2[p], bd[j], acc2[p][j]);
        }
    }
    __syncthreads();

    float* Cb = C + (size_t)b * sCb;
    #pragma unroll
    for (int p = 0; p < RP; p++) {
        int gm0 = m0 + r0 + 2 * p;
        float inv0 = 1.f / rsum[r0 + 2 * p];
        float inv1 = 1.f / rsum[r0 + 2 * p + 1];
        #pragma unroll
        for (int j = 0; j < CN; j++) {
            int gn = n0 + c0 + j;
            unsigned int ul, uh;
            UNPACK_F32X2(ul, uh, acc2[p][j]);
            Cb[(size_t)gm0 * sCm + gn]       = __uint_as_float(ul) * inv0;
            Cb[(size_t)(gm0 + 1) * sCm + gn] = __uint_as_float(uh) * inv1;
        }
    }
}

__global__ void __launch_bounds__(256) gat_pv_both(
    const float* __restrict__ F1F, const float* __restrict__ F2F,
    const float* __restrict__ Fadj, const float* __restrict__ WhF,
    float* __restrict__ Fat,
    const float* __restrict__ F1T, const float* __restrict__ F2T,
    const float* __restrict__ Tadj, const float* __restrict__ WhT,
    float* __restrict__ Tat)
{
    __shared__ float buf[4*128 + 96 + 256 + 32*136 + 32*64 + 128*33];
    if (blockIdx.z < 256) {
        if (blockIdx.y) return;
        gat_pv_impl<64,128,2,8>(buf, blockIdx.z, blockIdx.x, 0,
            F1F, F2F, Fadj, 4096LL, WhF, 16384LL, 256, 64,
            Fat, 16384LL, 256);
    } else {
        if (blockIdx.x) return;
        gat_pv_impl<128,64,4,4>(buf, blockIdx.z - 256, 0, blockIdx.y,
            F1T, F2T, Tadj, 65536LL, WhT, 16384LL, 64, 256,
            Tat, 16384LL, 64);
    }
}

// ---------------- gi GEMM v2 (R14) ---------------------------------------------
__global__ void __launch_bounds__(256) gi_gemm(
    const float* __restrict__ Fat, const float* __restrict__ Tat,
    const float* __restrict__ x,  const float* __restrict__ W,
    const float* __restrict__ bias, float* __restrict__ gi)
{
    int b = blockIdx.x;

    __shared__ float As[32 * 68];
    __shared__ float Bs[32 * 98];

    int tid = threadIdx.x;
    int tx = tid & 15, ty = tid >> 4;
    int r0 = ty * 4, c0 = tx * 6;

    const float* Wb = W + (size_t)b * 73728;

    unsigned long long acc2[2][6];
    #pragma unroll
    for (int p = 0; p < 2; p++)
        #pragma unroll
        for (int j = 0; j < 6; j++) acc2[p][j] = 0ull;

    for (int t = 0; t < 24; t++) {
        int k0 = t * 32;
        __syncthreads();
        if (k0 < 256 || k0 >= 512) {
            const float* S = (k0 < 256) ? (Fat + (size_t)b * 16384)
                                        : (x   + (size_t)b * 16384);
            int kb = (k0 < 256) ? k0 : (k0 - 512);
            #pragma unroll
            for (int l = 0; l < 2; l++) {
                int e = tid + l * 256;
                int m = e >> 3, kq = e & 7;
                float4 v = *(const float4*)&S[(size_t)m * 256 + kb + kq * 4];
                As[(kq * 4 + 0) * 68 + m] = v.x;
                As[(kq * 4 + 1) * 68 + m] = v.y;
                As[(kq * 4 + 2) * 68 + m] = v.z;
                As[(kq * 4 + 3) * 68 + m] = v.w;
            }
        } else {
            const float* S = Tat + (size_t)b * 16384;
            int kb = k0 - 256;
            #pragma unroll
            for (int l = 0; l < 8; l++) {
                int e = tid + l * 256;
                int m = e & 63, kk = e >> 6;
                As[kk * 68 + m] = S[(size_t)(kb + kk) * 64 + m];
            }
        }
        #pragma unroll
        for (int l = 0; l < 6; l++) {
            int e = tid + l * 256;
            int g = e >> 4, kp = e & 15;
            float2 v = *(const float2*)&Wb[(size_t)g * 768 + k0 + kp * 2];
            Bs[(kp * 2 + 0) * 98 + g] = v.x;
            Bs[(kp * 2 + 1) * 98 + g] = v.y;
        }
        __syncthreads();
        #pragma unroll
        for (int kk = 0; kk < 32; kk++) {
            ulonglong2 aa = *(const ulonglong2*)&As[kk * 68 + r0];
            unsigned long long a2[2] = {aa.x, aa.y};
            float2 b01 = *(const float2*)&Bs[kk * 98 + c0];
            float2 b23 = *(const float2*)&Bs[kk * 98 + c0 + 2];
            float2 b45 = *(const float2*)&Bs[kk * 98 + c0 + 4];
            float bv[6] = {b01.x, b01.y, b23.x, b23.y, b45.x, b45.y};
            unsigned long long bd[6];
            #pragma unroll
            for (int j = 0; j < 6; j++) {
                unsigned int u = __float_as_uint(bv[j]);
                PACK_F32X2(bd[j], u, u);
            }
            #pragma unroll
            for (int p = 0; p < 2; p++)
                #pragma unroll
                for (int j = 0; j < 6; j++)
                    FMA_F32X2(acc2[p][j], a2[p], bd[j], acc2[p][j]);
        }
    }

    const float* bb = bias + (size_t)b * 96;
    float* gb = gi + (size_t)b * 6144;
    #pragma unroll
    for (int p = 0; p < 2; p++) {
        int gm0 = r0 + 2 * p;
        #pragma unroll
        for (int j = 0; j < 6; j++) {
            int gn = c0 + j;
            unsigned int ul, uh;
            UNPACK_F32X2(ul, uh, acc2[p][j]);
            float bv = bb[gn];
            gb[(size_t)gm0 * 96 + gn]       = __uint_as_float(ul) + bv;
            gb[(size_t)(gm0 + 1) * 96 + gn] = __uint_as_float(uh) + bv;
        }
    }
}

// ---------------- GRU (R11/R14) -------------------------------------------------
__device__ __forceinline__ float fsigm(float x) {
    return __fdividef(1.f, 1.f + __expf(-x));
}
__device__ __forceinline__ float ftanh(float x) {
    return 2.f * __fdividef(1.f, 1.f + __expf(-2.f * x)) - 1.f;
}
__device__ __forceinline__ float hsum2(unsigned long long a) {
    unsigned int lo, hi;
    UNPACK_F32X2(lo, hi, a);
    return __uint_as_float(lo) + __uint_as_float(hi);
}

__global__ void __launch_bounds__(64) gru_kernel(
    const float* __restrict__ giAll,
    const float* __restrict__ Whh0, const float* __restrict__ bhh0,
    const float* __restrict__ Wih1, const float* __restrict__ bih1,
    const float* __restrict__ Whh1, const float* __restrict__ bhh1,
    const float* __restrict__ Hpre,
    float* __restrict__ gruOut, float* __restrict__ outCatH)
{
    int n = blockIdx.x;
    int lane = threadIdx.x & 31;
    int w = threadIdx.x >> 5;

    __shared__ __align__(16) float h0buf[2][32];
    __shared__ __align__(16) float h0cur[32];
    __shared__ __align__(16) float h1s[32];

    if (w == 0) {
        unsigned long long wr2[16], wz2[16], wn2[16];
        {
            const float4* pr = (const float4*)(Whh0 + (size_t)n * 3072 + lane * 32);
            const float4* pz = (const float4*)(Whh0 + (size_t)n * 3072 + (32 + lane) * 32);
            const float4* pn = (const float4*)(Whh0 + (size_t)n * 3072 + (64 + lane) * 32);
            #pragma unroll
            for (int q = 0; q < 8; q++) {
                float4 a = pr[q], bq = pz[q], c = pn[q];
                PACK_F32X2(wr2[2*q],   __float_as_uint(a.x),  __float_as_uint(a.y));
                PACK_F32X2(wr2[2*q+1], __float_as_uint(a.z),  __float_as_uint(a.w));
                PACK_F32X2(wz2[2*q],   __float_as_uint(bq.x), __float_as_uint(bq.y));
                PACK_F32X2(wz2[2*q+1], __float_as_uint(bq.z), __float_as_uint(bq.w));
                PACK_F32X2(wn2[2*q],   __float_as_uint(c.x),  __float_as_uint(c.y));
                PACK_F32X2(wn2[2*q+1], __float_as_uint(c.z),  __float_as_uint(c.w));
            }
        }
        float bhr = bhh0[(size_t)n * 96 + lane];
        float bhz = bhh0[(size_t)n * 96 + 32 + lane];
        float bhn = bhh0[(size_t)n * 96 + 64 + lane];
        float h0 = Hpre[(size_t)n * 32 + lane];
        h0cur[lane] = h0;
        __syncwarp();

        const float* gin = giAll + (size_t)n * 6144;
        float gir = gin[lane], giz = gin[32 + lane], ginn = gin[64 + lane];

        for (int t = 0; t < SS; t++) {
            unsigned long long ar2 = 0ull, az2 = 0ull, an2 = 0ull;
            const ulonglong2* hp = (const ulonglong2*)h0cur;
            #pragma unroll
            for (int q = 0; q < 8; q++) {
                ulonglong2 hv = hp[q];
                FMA_F32X2(ar2, wr2[2*q],   hv.x, ar2);
                FMA_F32X2(az2, wz2[2*q],   hv.x, az2);
                FMA_F32X2(an2, wn2[2*q],   hv.x, an2);
                FMA_F32X2(ar2, wr2[2*q+1], hv.y, ar2);
                FMA_F32X2(az2, wz2[2*q+1], hv.y, az2);
                FMA_F32X2(an2, wn2[2*q+1], hv.y, an2);
            }
            float r = fsigm(gir + bhr + hsum2(ar2));
            float z = fsigm(giz + bhz + hsum2(az2));
            float nn = ftanh(ginn + r * (bhn + hsum2(an2)));
            h0 = (1.f - z) * nn + z * h0;
            if (t + 1 < SS) {
                gir  = gin[(t + 1) * 96 + lane];
                giz  = gin[(t + 1) * 96 + 32 + lane];
                ginn = gin[(t + 1) * 96 + 64 + lane];
            }
            __syncwarp();
            h0cur[lane] = h0;
            h0buf[t & 1][lane] = h0;
            __syncwarp();
            __syncthreads();
        }
        outCatH[(size_t)n * 32 + lane] = h0;
    } else {
        unsigned long long vr2[16], vz2[16], vn2[16], ur2[16], uz2[16], un2[16];
        {
            const float4* p0 = (const float4*)(Wih1 + (size_t)n * 3072 + lane * 32);
            const float4* p1 = (const float4*)(Wih1 + (size_t)n * 3072 + (32 + lane) * 32);
            const float4* p2 = (const float4*)(Wih1 + (size_t)n * 3072 + (64 + lane) * 32);
            const float4* p3 = (const float4*)(Whh1 + (size_t)n * 3072 + lane * 32);
            const float4* p4 = (const float4*)(Whh1 + (size_t)n * 3072 + (32 + lane) * 32);
            const float4* p5 = (const float4*)(Whh1 + (size_t)n * 3072 + (64 + lane) * 32);
            #pragma unroll
            for (int q = 0; q < 8; q++) {
                float4 a = p0[q], bq = p1[q], c = p2[q], d = p3[q], e = p4[q], f = p5[q];
                PACK_F32X2(vr2[2*q],   __float_as_uint(a.x),  __float_as_uint(a.y));
                PACK_F32X2(vr2[2*q+1], __float_as_uint(a.z),  __float_as_uint(a.w));
                PACK_F32X2(vz2[2*q],   __float_as_uint(bq.x), __float_as_uint(bq.y));
                PACK_F32X2(vz2[2*q+1], __float_as_uint(bq.z), __float_as_uint(bq.w));
                PACK_F32X2(vn2[2*q],   __float_as_uint(c.x),  __float_as_uint(c.y));
                PACK_F32X2(vn2[2*q+1], __float_as_uint(c.z),  __float_as_uint(c.w));
                PACK_F32X2(ur2[2*q],   __float_as_uint(d.x),  __float_as_uint(d.y));
                PACK_F32X2(ur2[2*q+1], __float_as_uint(d.z),  __float_as_uint(d.w));
                PACK_F32X2(uz2[2*q],   __float_as_uint(e.x),  __float_as_uint(e.y));
                PACK_F32X2(uz2[2*q+1], __float_as_uint(e.z),  __float_as_uint(e.w));
                PACK_F32X2(un2[2*q],   __float_as_uint(f.x),  __float_as_uint(f.y));
                PACK_F32X2(un2[2*q+1], __float_as_uint(f.z),  __float_as_uint(f.w));
            }
        }
        float bir = bih1[(size_t)n * 96 + lane];
        float biz = bih1[(size_t)n * 96 + 32 + lane];
        float bin = bih1[(size_t)n * 96 + 64 + lane];
        float bhr = bhh1[(size_t)n * 96 + lane];
        float bhz = bhh1[(size_t)n * 96 + 32 + lane];
        float bhn = bhh1[(size_t)n * 96 + 64 + lane];
        float h1 = Hpre[8192 + (size_t)n * 32 + lane];
        h1s[lane] = h1;
        __syncwarp();

        float* outp = gruOut + (size_t)n * SS * 32 + lane;

        for (int t = 0; t < SS; t++) {
            __syncthreads();
            const ulonglong2* xp = (const ulonglong2*)h0buf[t & 1];
            const ulonglong2* hp = (const ulonglong2*)h1s;
            unsigned long long ar2 = 0ull, az2 = 0ull, an2 = 0ull;
            unsigned long long cr2 = 0ull, cz2 = 0ull, cn2 = 0ull;
            #pragma unroll
            for (int q = 0; q < 8; q++) {
                ulonglong2 xv = xp[q];
                ulonglong2 hv = hp[q];
                FMA_F32X2(ar2, vr2[2*q],   xv.x, ar2);
                FMA_F32X2(az2, vz2[2*q],   xv.x, az2);
                FMA_F32X2(an2, vn2[2*q],   xv.x, an2);
                FMA_F32X2(cr2, ur2[2*q],   hv.x, cr2);
                FMA_F32X2(cz2, uz2[2*q],   hv.x, cz2);
                FMA_F32X2(cn2, un2[2*q],   hv.x, cn2);
                FMA_F32X2(ar2, vr2[2*q+1], xv.y, ar2);
                FMA_F32X2(az2, vz2[2*q+1], xv.y, az2);
                FMA_F32X2(an2, vn2[2*q+1], xv.y, an2);
                FMA_F32X2(cr2, ur2[2*q+1], hv.y, cr2);
                FMA_F32X2(cz2, uz2[2*q+1], hv.y, cz2);
                FMA_F32X2(cn2, un2[2*q+1], hv.y, cn2);
            }
            float r = fsigm(bir + bhr + hsum2(ar2) + hsum2(cr2));
            float z = fsigm(biz + bhz + hsum2(az2) + hsum2(cz2));
            float nn = ftanh(bin + hsum2(an2) + r * (bhn + hsum2(cn2)));
            h1 = (1.f - z) * nn + z * h1;
            __syncwarp();
            h1s[lane] = h1;
            __syncwarp();
            outp[t * 32] = h1;
        }
        outCatH[8192 + (size_t)n * 32 + lane] = h1;
    }
}

// ---------------- fused fc1+fc2+fc3 (unchanged) --------------------------------
__global__ void fc_fused(const float* __restrict__ gru,
                         const float* __restrict__ W1, const float* __restrict__ b1,
                         const float* __restrict__ W2, const float* __restrict__ b2,
                         const float* __restrict__ w3, const float* __restrict__ b3,
                         float* __restrict__ ct)
{
    int n = blockIdx.x;
    int tid = threadIdx.x;
    int warp = tid >> 5, lane = tid & 31;
    __shared__ float W1s[32 * 33], W2s[32 * 33];
    __shared__ float w3s[32], b1s[32], b2s[32];
    __shared__ float xs[8][33];

    for (int idx = tid; idx < 1024; idx += 256) {
        int r = idx >> 5, c = idx & 31;
        W1s[r * 33 + c] = W1[(size_t)n * 1024 + idx];
        W2s[r * 33 + c] = W2[(size_t)n * 1024 + idx];
    }
    if (tid < 32) {
        w3s[tid] = w3[(size_t)n * 32 + tid];
        b1s[tid] = b1[(size_t)n * 32 + tid];
        b2s[tid] = b2[(size_t)n * 32 + tid];
    }
    __syncthreads();
    float b3v = b3[n];

    for (int s = warp; s < 64; s += 8) {
        float xv = gru[((size_t)n * 64 + s) * 32 + lane];
        xs[warp][lane] = xv;
        __syncwarp();
        float h1 = b1s[lane];
        #pragma unroll
        for (int j = 0; j < 32; j++) h1 += W1s[lane * 33 + j] * xs[warp][j];
        h1 = fmaxf(h1, 0.f);
        __syncwarp();
        xs[warp][lane] = h1;
        __syncwarp();
        float h2 = b2s[lane];
        #pragma unroll
        for (int j = 0; j < 32; j++) h2 += W2s[lane * 33 + j] * xs[warp][j];
        h2 = fmaxf(h2, 0.f);
        float p = h2 * w3s[lane];
        #pragma unroll
        for (int o = 16; o; o >>= 1) p += __shfl_xor_sync(0xffffffffu, p, o);
        if (lane == 0) ct[(size_t)n * 64 + s] = p + b3v;
        __syncwarp();
    }
}

// ---------------- whole-GAT-per-block output stage (unchanged) ------------------
__global__ void __launch_bounds__(1024) out_gat(
    const float* __restrict__ inp, int inStride, int Kd,
    const float* __restrict__ W0, const float* __restrict__ a0,
    const float* __restrict__ W1, const float* __restrict__ a1,
    const float* __restrict__ adj,
    float* __restrict__ outp, int outRowStride)
{
    const float* Wm = (blockIdx.y == 0) ? W0 : W1;
    const float* av = (blockIdx.y == 0) ? a0 : a1;
    int dstOff = blockIdx.y * 64;
    int mBase = blockIdx.x * 32;

    extern __shared__ float sm[];
    float* WhS = sm;
    float* WS  = WhS + 256 * 65;
    float* ctC = WS + 64 * (Kd + 4);
    float* aS  = ctC + 64 * Kd;
    float* e1  = aS + 128;
    float* e1p = e1 + 256;
    float* e2  = e1p + 256;
    float* e2p = e2 + 256;
    float* f1  = e2p + 256;
    float* f2  = f1 + 256;
    float* pb  = f2 + 256;

    int tid = threadIdx.x;
    for (int i = tid; i < 64 * Kd; i += 1024) {
        int g = i / Kd, k = i % Kd;
        WS[g * (Kd + 4) + k] = Wm[(size_t)k * 64 + g];
    }
    if (tid < 128) aS[tid] = av[tid];

    int g = tid & 63, mq = tid >> 6;
    for (int ch = 0; ch < 4; ch++) {
        __syncthreads();
        for (int i = tid; i < 64 * Kd; i += 1024)
            ctC[i] = inp[(size_t)(ch * 64 + i / Kd) * inStride + (i % Kd)];
        __syncthreads();
        float acc[4] = {0.f, 0.f, 0.f, 0.f};
        for (int k = 0; k < Kd; k += 4) {
            float4 wv = *(const float4*)&WS[g * (Kd + 4) + k];
            #pragma unroll
            for (int rr = 0; rr < 4; rr++) {
                float4 cv = *(const float4*)&ctC[(mq * 4 + rr) * Kd + k];
                acc[rr] += cv.x * wv.x + cv.y * wv.y + cv.z * wv.z + cv.w * wv.w;
            }
        }
        #pragma unroll
        for (int rr = 0; rr < 4; rr++)
            WhS[(ch * 64 + mq * 4 + rr) * 65 + g] = acc[rr];
    }
    __syncthreads();
    if (tid < 256) {
        float s1 = 0.f, s2 = 0.f;
        #pragma unroll
        for (int c = 0; c < 64; c++) {
            float w = WhS[tid * 65 + c];
            s1 += w * aS[c];
            s2 += w * aS[64 + c];
        }
        f1[tid] = s1; f2[tid] = s2;
        e1[tid] = __expf(s1); e1p[tid] = __expf(0.2f * s1);
        e2[tid] = __expf(s2); e2p[tid] = __expf(0.2f * s2);
    }
    __syncthreads();

    int w = tid >> 5, lane = tid & 31;
    {
        int m = mBase + w;
        const float* adjrow = adj + (size_t)m * 256;
        float f1m = f1[m], E1m = e1[m], E1pm = e1p[m];
        float s = 0.f;
        for (int k = lane; k < 256; k += 32) {
            float f = f1m + f2[k];
            float p = (f >= 0.f) ? E1m * e2[k] : E1pm * e2p[k];
            p = (adjrow[k] > 0.f) ? p : 0.f;
            pb[w * 256 + k] = p;
            s += p;
        }
        #pragma unroll
        for (int o = 16; o; o >>= 1) s += __shfl_xor_sync(0xffffffffu, s, o);
        float inv = 1.f / s;
        __syncwarp();
        #pragma unroll
        for (int c0 = 0; c0 < 64; c0 += 32) {
            int c = c0 + lane;
            float acc0 = 0.f, acc1 = 0.f;
            for (int k = 0; k < 256; k += 4) {
                float4 p4 = *(const float4*)&pb[w * 256 + k];
                acc0 += p4.x * WhS[(k + 0) * 65 + c] + p4.z * WhS[(k + 2) * 65 + c];
                acc1 += p4.y * WhS[(k + 1) * 65 + c] + p4.w * WhS[(k + 3) * 65 + c];
            }
            outp[(size_t)m * outRowStride + dstOff + c] = (acc0 + acc1) * inv;
        }
    }
}

// ---------------- launch -------------------------------------------------------
extern "C" void kernel_launch(void* const* d_in, const int* in_sizes, int n_in,
                              void* d_out, int out_size)
{
    const float* x     = (const float*)d_in[0];
    const float* Fadj  = (const float*)d_in[1];
    const float* Tadj  = (const float*)d_in[2];
    const float* adj   = (const float*)d_in[3];
    const float* Hpre  = (const float*)d_in[4];
    const float* FattW = (const float*)d_in[5];
    const float* Fatta = (const float*)d_in[6];
    const float* TattW = (const float*)d_in[7];
    const float* Tatta = (const float*)d_in[8];
    const float* Wih0  = (const float*)d_in[9];
    const float* Whh0  = (const float*)d_in[10];
    const float* bih0  = (const float*)d_in[11];
    const float* bhh0  = (const float*)d_in[12];
    const float* Wih1  = (const float*)d_in[13];
    const float* Whh1  = (const float*)d_in[14];
    const float* bih1  = (const float*)d_in[15];
    const float* bhh1  = (const float*)d_in[16];
    const float* fc1w  = (const float*)d_in[17];
    const float* fc1b  = (const float*)d_in[18];
    const float* fc2w  = (const float*)d_in[19];
    const float* fc2b  = (const float*)d_in[20];
    const float* fc3w  = (const float*)d_in[21];
    const float* fc3b  = (const float*)d_in[22];
    const float* oW    = (const float*)d_in[23];
    const float* oa    = (const float*)d_in[24];
    const float* o1W   = (const float*)d_in[25];
    const float* o1a   = (const float*)d_in[26];
    const float* o2W   = (const float*)d_in[27];
    const float* o2a   = (const float*)d_in[28];
    float* out = (float*)d_out;

    float *WhF, *WhT, *Tat, *Fat, *gi, *gru, *ct, *cat2, *Fb;
    cudaGetSymbolAddress((void**)&WhF,  g_WhF);
    cudaGetSymbolAddress((void**)&WhT,  g_WhT);
    cudaGetSymbolAddress((void**)&Tat,  g_Tat);
    cudaGetSymbolAddress((void**)&Fat,  g_Fat);
    cudaGetSymbolAddress((void**)&gi,   g_gi);
    cudaGetSymbolAddress((void**)&gru,  g_gru);
    cudaGetSymbolAddress((void**)&ct,   g_ct);
    cudaGetSymbolAddress((void**)&cat2, g_cat2);
    cudaGetSymbolAddress((void**)&Fb,   g_F);
    float* F1F = Fb;
    float* F2F = Fb + NN * WWIN;
    float* F1T = Fb + 2 * NN * WWIN;
    float* F2T = Fb + 3 * NN * WWIN;

    cudaFuncSetAttribute(out_gat, cudaFuncAttributeMaxDynamicSharedMemorySize, 180224);

    // 1. zero f1/f2 accumulators
    cudaMemsetAsync(Fb, 0, 4 * NN * WWIN * sizeof(float));

    // 2. both Wh GEMMs (Feature + Time) in one launch
    gemm_wh_both<<<dim3(2, 2, 512), 256>>>(x, FattW, Fatta, TattW, Tatta,
                                           WhF, WhT, F1F, F2F, F1T, F2T);

    // 3. both softmax+PV in one launch (double-buffered)
    gat_pv_both<<<dim3(2, 2, 512), 256>>>(F1F, F2F, Fadj, WhF, Fat,
                                          F1T, F2T, Tadj, WhT, Tat);

    // 4. gi = [Fat | Tat^T | x] @ Wih0^T + bih0
    gi_gemm<<<256, 256>>>(Fat, Tat, x, Wih0, bih0, gi);

    // 5. GRU recurrence (cat_H -> d_out[16384:])
    gru_kernel<<<256, 64>>>(gi, Whh0, bhh0, Wih1, bih1, Whh1, bhh1, Hpre,
                            gru, out + 16384);

    // 6. FC stack -> ct
    fc_fused<<<256, 256>>>(gru, fc1w, fc1b, fc2w, fc2b, fc3w, fc3b, ct);

    // 7. output GATs out/out1 -> cat2
    {
        size_t smem = (256*65 + 64*68 + 64*64 + 128 + 6*256 + 32*256) * sizeof(float);
        out_gat<<<dim3(8, 2), 1024, smem>>>(ct, 64, 64, oW, oa, o1W, o1a,
                                            adj, cat2, 128);
    }
    // 8. final GAT -> d_out[0:16384]
    {
        size_t smem = (256*65 + 64*132 + 64*128 + 128 + 6*256 + 32*256) * sizeof(float);
        out_gat<<<dim3(8, 1), 1024, smem>>>(cat2, 128, 128, o2W, o2a, o2W, o2a,
                                            adj, out, 64);
    }
}

// round 16
// speedup vs baseline: 1.0503x; 1.0503x over previous
#include <cuda_runtime.h>
#include <math.h>

#define NN 256
#define SS 64
#define WWIN 256
#define HH 32

// ---------------- scratch ------------------------------------------------------
__device__ float g_WhF[NN*SS*WWIN];
__device__ float g_WhT[NN*WWIN*SS];
__device__ float g_Tat[NN*WWIN*SS];
__device__ float g_Fat[NN*SS*WWIN];
__device__ float g_gi[NN*SS*96];
__device__ float g_gru[NN*SS*HH];
__device__ float g_ct[NN*SS];
__device__ float g_cat2[NN*2*SS];
__device__ float g_F[4*NN*WWIN];       // F1F | F2F | F1T | F2T

#define FMA_F32X2(d, a, b, c) \
    asm("fma.rn.f32x2 %0, %1, %2, %3;" : "=l"(d) : "l"(a), "l"(b), "l"(c))
#define PACK_F32X2(out, lo, hi) \
    asm("mov.b64 %0, {%1, %2};" : "=l"(out) : "r"(lo), "r"(hi))
#define UNPACK_F32X2(lo, hi, in) \
    asm("mov.b64 {%0, %1}, %2;" : "=r"(lo), "=r"(hi) : "l"(in))

// ---------------- gemm_wh impl (device) ----------------------------------------
template<int BM, int BN>
__device__ __forceinline__ void gemm_wh_impl(
    float* smem, int b, int bx, int by,
    const float* __restrict__ A, const float* __restrict__ B,
    float* __restrict__ C,
    int M, int N, int K,
    long long sAb, int sAm, int sAk,
    long long sBb, int sBk, int sBn,
    long long sCb, int sCm,
    const float* __restrict__ avec, long long aStride,
    float* __restrict__ F1o, float* __restrict__ F2o)
{
    constexpr int TX = BN / 8;
    constexpr int LA = BM * 16 / 256;
    constexpr int LB = BN * 16 / 256;

    int m0 = by * BM;
    int n0 = bx * BN;
    const float* Ab = A + (size_t)b * sAb;
    const float* Bb = B + (size_t)b * sBb;
    float*       Cb = C + (size_t)b * sCb;

    float (*As)[BM] = (float(*)[BM])smem;
    float (*Bs)[BN] = (float(*)[BN])(smem + 16 * BM);

    int tid = threadIdx.x;
    int tx = tid % TX, ty = tid / TX;
    int r0  = ty * 4;
    int c0a = tx * 4;
    int c0b = BN / 2 + tx * 4;
    bool aK1 = (sAk == 1);

    unsigned long long acc2[2][8];
    #pragma unroll
    for (int p = 0; p < 2; p++)
        #pragma unroll
        for (int j = 0; j < 8; j++) acc2[p][j] = 0ull;

    auto loadA = [&](int k0, float r[LA]) {
        if (aK1) {
            #pragma unroll
            for (int l = 0; l < LA; l++) {
                int e = tid + l * 256; int m = e >> 4, kk = e & 15;
                r[l] = Ab[(size_t)(m0 + m) * sAm + (k0 + kk)];
            }
        } else {
            #pragma unroll
            for (int l = 0; l < LA; l++) {
                int e = tid + l * 256; int m = e % BM, kk = e / BM;
                r[l] = Ab[(size_t)(m0 + m) + (size_t)(k0 + kk) * sAk];
            }
        }
    };
    auto storeA = [&](float r[LA]) {
        if (aK1) {
            #pragma unroll
            for (int l = 0; l < LA; l++) { int e = tid + l * 256; As[e & 15][e >> 4] = r[l]; }
        } else {
            #pragma unroll
            for (int l = 0; l < LA; l++) { int e = tid + l * 256; As[e / BM][e % BM] = r[l]; }
        }
    };
    auto loadB = [&](int k0, float r[LB]) {
        #pragma unroll
        for (int l = 0; l < LB; l++) {
            int e = tid + l * 256; int n = e % BN, kk = e / BN; int gn = n0 + n;
            r[l] = Bb[(size_t)(k0 + kk) * sBk + (size_t)gn * sBn];
        }
    };
    auto storeB = [&](float r[LB]) {
        #pragma unroll
        for (int l = 0; l < LB; l++) { int e = tid + l * 256; Bs[e / BN][e % BN] = r[l]; }
    };

    float ra[LA], rb[LB], na[LA], nb[LB];
    loadA(0, ra); loadB(0, rb);

    for (int k0 = 0; k0 < K; k0 += 16) {
        storeA(ra); storeB(rb);
        __syncthreads();
        if (k0 + 16 < K) { loadA(k0 + 16, na); loadB(k0 + 16, nb); }
        #pragma unroll
        for (int kk = 0; kk < 16; kk++) {
            ulonglong2 a01 = *(const ulonglong2*)&As[kk][r0];
            unsigned long long a2[2] = {a01.x, a01.y};
            float4 bA = *(const float4*)&Bs[kk][c0a];
            float4 bB = *(const float4*)&Bs[kk][c0b];
            float bv[8] = {bA.x, bA.y, bA.z, bA.w, bB.x, bB.y, bB.z, bB.w};
            unsigned long long bd[8];
            #pragma unroll
            for (int j = 0; j < 8; j++) {
                unsigned int u = __float_as_uint(bv[j]);
                PACK_F32X2(bd[j], u, u);
            }
            #pragma unroll
            for (int p = 0; p < 2; p++)
                #pragma unroll
                for (int j = 0; j < 8; j++)
                    FMA_F32X2(acc2[p][j], a2[p], bd[j], acc2[p][j]);
        }
        __syncthreads();
        #pragma unroll
        for (int l = 0; l < LA; l++) ra[l] = na[l];
        #pragma unroll
        for (int l = 0; l < LB; l++) rb[l] = nb[l];
    }

    #pragma unroll
    for (int p = 0; p < 2; p++) {
        int gm0 = m0 + r0 + 2 * p;
        #pragma unroll
        for (int j = 0; j < 8; j++) {
            int gn = n0 + ((j < 4) ? (c0a + j) : (c0b + j - 4));
            unsigned int ul, uh;
            UNPACK_F32X2(ul, uh, acc2[p][j]);
            Cb[(size_t)gm0 * sCm + gn]       = __uint_as_float(ul);
            Cb[(size_t)(gm0 + 1) * sCm + gn] = __uint_as_float(uh);
        }
    }
    {
        const float* ab = avec + (size_t)b * aStride;
        float a1v[8], a2v[8];
        #pragma unroll
        for (int j = 0; j < 8; j++) {
            int gn = n0 + ((j < 4) ? (c0a + j) : (c0b + j - 4));
            a1v[j] = ab[gn];
            a2v[j] = ab[N + gn];
        }
        #pragma unroll
        for (int p = 0; p < 2; p++) {
            float s1l = 0.f, s1h = 0.f, s2l = 0.f, s2h = 0.f;
            #pragma unroll
            for (int j = 0; j < 8; j++) {
                unsigned int ul, uh;
                UNPACK_F32X2(ul, uh, acc2[p][j]);
                float v0 = __uint_as_float(ul), v1 = __uint_as_float(uh);
                s1l += v0 * a1v[j]; s1h += v1 * a1v[j];
                s2l += v0 * a2v[j]; s2h += v1 * a2v[j];
            }
            #pragma unroll
            for (int o = TX >> 1; o; o >>= 1) {
                s1l += __shfl_xor_sync(0xffffffffu, s1l, o);
                s1h += __shfl_xor_sync(0xffffffffu, s1h, o);
                s2l += __shfl_xor_sync(0xffffffffu, s2l, o);
                s2h += __shfl_xor_sync(0xffffffffu, s2h, o);
            }
            if (tx == 0) {
                int gm0 = m0 + r0 + 2 * p;
                atomicAdd(&F1o[(size_t)b * M + gm0],     s1l);
                atomicAdd(&F1o[(size_t)b * M + gm0 + 1], s1h);
                atomicAdd(&F2o[(size_t)b * M + gm0],     s2l);
                atomicAdd(&F2o[(size_t)b * M + gm0 + 1], s2h);
            }
        }
    }
}

// compact grid: z in [0,1024). z<512 -> Feature (b=z>>1, bx=z&1);
// z>=512 -> Time (b=(z-512)>>1, by=z&1). No empty blocks.
__global__ void __launch_bounds__(256, 2) gemm_wh_both(
    const float* __restrict__ x,
    const float* __restrict__ FattW, const float* __restrict__ Fatta,
    const float* __restrict__ TattW, const float* __restrict__ Tatta,
    float* __restrict__ WhF, float* __restrict__ WhT,
    float* __restrict__ F1F, float* __restrict__ F2F,
    float* __restrict__ F1T, float* __restrict__ F2T)
{
    __shared__ float smem[16 * 64 + 16 * 128];
    int idx = blockIdx.z;
    if (idx < 512) {
        gemm_wh_impl<64,128>(smem, idx >> 1, idx & 1, 0,
            x, FattW, WhF, 64, 256, 256,
            16384LL, 256, 1,  65536LL, 256, 1,  16384LL, 256,
            Fatta, 512LL, F1F, F2F);
    } else {
        int j = idx - 512;
        gemm_wh_impl<128,64>(smem, j >> 1, 0, j & 1,
            x, TattW, WhT, 256, 64, 64,
            16384LL, 1, 256,  4096LL, 64, 1,  16384LL, 64,
            Tatta, 128LL, F1T, F2T);
    }
}

// ---------------- gat_pv impl (device): wide tiles (R14 config) -----------------
template<int BM, int BN, int RP, int CN>
__device__ __forceinline__ void gat_pv_impl(
    float* buf, int b, int bx, int by,
    const float* __restrict__ F1, const float* __restrict__ F2,
    const float* __restrict__ adj, long long adjBStride,
    const float* __restrict__ V, long long sVb, int sVm,
    int M,
    float* __restrict__ C, long long sCb, int sCm)
{
    constexpr int PS = BM + 8;
    constexpr int G  = 256 / BM;
    constexpr int KP = 32 / G;
    constexpr int TX = BN / CN;
    int m0 = by * BM;
    int n0 = bx * BN;

    float* f1s  = buf;
    float* Ae   = buf + BM;
    float* Ape  = buf + 2 * BM;
    float* rsum = buf + 3 * BM;
    float* f2s  = buf + 4 * BM;
    float* Bks  = f2s + 32;
    float* Bkps = f2s + 64;
    float* rs   = f2s + 96;
    float* Pt   = rs + 256;
    float* Bt   = Pt + 32 * PS;
    float* adjS = Bt + 32 * BN;

    int tid = threadIdx.x;
    int tx = tid % TX, ty = tid / TX;
    int r0 = ty * 2 * RP, c0 = tx * CN;

    size_t base = (size_t)b * M;
    if (tid < BM) {
        float f = F1[base + m0 + tid];
        f1s[tid] = f;
        Ae[tid]  = __expf(f);
        Ape[tid] = __expf(0.2f * f);
        rsum[tid] = 0.f;
    }

    const float* adjb = adj + (size_t)b * adjBStride;
    const float* Vb   = V + (size_t)b * sVb;

    unsigned long long acc2[RP][CN];
    #pragma unroll
    for (int p = 0; p < RP; p++)
        #pragma unroll
        for (int j = 0; j < CN; j++) acc2[p][j] = 0ull;

    int mP = tid % BM;
    int kg = tid / BM;

    for (int k0 = 0; k0 < M; k0 += 32) {
        __syncthreads();
        if (tid < 32) {
            float f = F2[base + k0 + tid];
            f2s[tid]  = f;
            Bks[tid]  = __expf(f);
            Bkps[tid] = __expf(0.2f * f);
        }
        #pragma unroll
        for (int l = 0; l < 32 * BN / 256; l++) {
            int e = tid + l * 256;
            int n = e % BN, kk = e / BN;
            Bt[kk * BN + n] = Vb[(size_t)(k0 + kk) * sVm + n0 + n];
        }
        #pragma unroll
        for (int l = 0; l < BM * 32 / 256; l++) {
            int e = tid + l * 256;
            int m = e >> 5, kk = e & 31;
            adjS[m * 33 + kk] = adjb[(size_t)(m0 + m) * M + k0 + kk];
        }
        __syncthreads();
        float part = 0.f;
        {
            float f1m = f1s[mP], Em = Ae[mP], Epm = Ape[mP];
            #pragma unroll
            for (int l = 0; l < KP; l++) {
                int kk = kg * KP + l;
                float av = adjS[mP * 33 + kk];
                float f = f1m + f2s[kk];
                float p = (f >= 0.f) ? Em * Bks[kk] : Epm * Bkps[kk];
                p = (av > 0.f) ? p : 0.f;
                Pt[kk * PS + mP] = p;
                part += p;
            }
        }
        rs[tid] = part;
        __syncthreads();
        if (tid < BM) {
            float s = 0.f;
            #pragma unroll
            for (int g = 0; g < G; g++) s += rs[g * BM + tid];
            rsum[tid] += s;
        }
        #pragma unroll
        for (int kk = 0; kk < 32; kk++) {
            unsigned long long a2[RP];
            #pragma unroll
            for (int q = 0; q < RP / 2; q++) {
                ulonglong2 aa = *(const ulonglong2*)&Pt[kk * PS + r0 + q * 4];
                a2[2 * q] = aa.x; a2[2 * q + 1] = aa.y;
            }
            float bv[CN];
            #pragma unroll
            for (int q = 0; q < CN / 4; q++) {
                float4 b4 = *(const float4*)&Bt[kk * BN + c0 + q * 4];
                bv[4 * q] = b4.x; bv[4 * q + 1] = b4.y; bv[4 * q + 2] = b4.z; bv[4 * q + 3] = b4.w;
            }
            unsigned long long bd[CN];
            #pragma unroll
            for (int j = 0; j < CN; j++) {
                unsigned int u = __float_as_uint(bv[j]);
                PACK_F32X2(bd[j], u, u);
            }
            #pragma unroll
            for (int p = 0; p < RP; p++)
                #pragma unroll
                for (int j = 0; j < CN; j++)
                    FMA_F32X2(acc2[p][j], a2[p], bd[j], acc2[p][j]);
        }
    }
    __syncthreads();

    float* Cb = C + (size_t)b * sCb;
    #pragma unroll
    for (int p = 0; p < RP; p++) {
        int gm0 = m0 + r0 + 2 * p;
        float inv0 = 1.f / rsum[r0 + 2 * p];
        float inv1 = 1.f / rsum[r0 + 2 * p + 1];
        #pragma unroll
        for (int j = 0; j < CN; j++) {
            int gn = n0 + c0 + j;
            unsigned int ul, uh;
            UNPACK_F32X2(ul, uh, acc2[p][j]);
            Cb[(size_t)gm0 * sCm + gn]       = __uint_as_float(ul) * inv0;
            Cb[(size_t)(gm0 + 1) * sCm + gn] = __uint_as_float(uh) * inv1;
        }
    }
}

__global__ void __launch_bounds__(256) gat_pv_both(
    const float* __restrict__ F1F, const float* __restrict__ F2F,
    const float* __restrict__ Fadj, const float* __restrict__ WhF,
    float* __restrict__ Fat,
    const float* __restrict__ F1T, const float* __restrict__ F2T,
    const float* __restrict__ Tadj, const float* __restrict__ WhT,
    float* __restrict__ Tat)
{
    __shared__ float buf[4*128 + 96 + 256 + 32*136 + 32*64 + 128*33];
    int idx = blockIdx.z;
    if (idx < 512) {
        gat_pv_impl<64,128,2,8>(buf, idx >> 1, idx & 1, 0,
            F1F, F2F, Fadj, 4096LL, WhF, 16384LL, 256, 64,
            Fat, 16384LL, 256);
    } else {
        int j = idx - 512;
        gat_pv_impl<128,64,4,4>(buf, j >> 1, 0, j & 1,
            F1T, F2T, Tadj, 65536LL, WhT, 16384LL, 64, 256,
            Tat, 16384LL, 64);
    }
}

// ---------------- gi GEMM v2 (R14) ---------------------------------------------
__global__ void __launch_bounds__(256) gi_gemm(
    const float* __restrict__ Fat, const float* __restrict__ Tat,
    const float* __restrict__ x,  const float* __restrict__ W,
    const float* __restrict__ bias, float* __restrict__ gi)
{
    int b = blockIdx.x;

    __shared__ float As[32 * 68];
    __shared__ float Bs[32 * 98];

    int tid = threadIdx.x;
    int tx = tid & 15, ty = tid >> 4;
    int r0 = ty * 4, c0 = tx * 6;

    const float* Wb = W + (size_t)b * 73728;

    unsigned long long acc2[2][6];
    #pragma unroll
    for (int p = 0; p < 2; p++)
        #pragma unroll
        for (int j = 0; j < 6; j++) acc2[p][j] = 0ull;

    for (int t = 0; t < 24; t++) {
        int k0 = t * 32;
        __syncthreads();
        if (k0 < 256 || k0 >= 512) {
            const float* S = (k0 < 256) ? (Fat + (size_t)b * 16384)
                                        : (x   + (size_t)b * 16384);
            int kb = (k0 < 256) ? k0 : (k0 - 512);
            #pragma unroll
            for (int l = 0; l < 2; l++) {
                int e = tid + l * 256;
                int m = e >> 3, kq = e & 7;
                float4 v = *(const float4*)&S[(size_t)m * 256 + kb + kq * 4];
                As[(kq * 4 + 0) * 68 + m] = v.x;
                As[(kq * 4 + 1) * 68 + m] = v.y;
                As[(kq * 4 + 2) * 68 + m] = v.z;
                As[(kq * 4 + 3) * 68 + m] = v.w;
            }
        } else {
            const float* S = Tat + (size_t)b * 16384;
            int kb = k0 - 256;
            #pragma unroll
            for (int l = 0; l < 8; l++) {
                int e = tid + l * 256;
                int m = e & 63, kk = e >> 6;
                As[kk * 68 + m] = S[(size_t)(kb + kk) * 64 + m];
            }
        }
        #pragma unroll
        for (int l = 0; l < 6; l++) {
            int e = tid + l * 256;
            int g = e >> 4, kp = e & 15;
            float2 v = *(const float2*)&Wb[(size_t)g * 768 + k0 + kp * 2];
            Bs[(kp * 2 + 0) * 98 + g] = v.x;
            Bs[(kp * 2 + 1) * 98 + g] = v.y;
        }
        __syncthreads();
        #pragma unroll
        for (int kk = 0; kk < 32; kk++) {
            ulonglong2 aa = *(const ulonglong2*)&As[kk * 68 + r0];
            unsigned long long a2[2] = {aa.x, aa.y};
            float2 b01 = *(const float2*)&Bs[kk * 98 + c0];
            float2 b23 = *(const float2*)&Bs[kk * 98 + c0 + 2];
            float2 b45 = *(const float2*)&Bs[kk * 98 + c0 + 4];
            float bv[6] = {b01.x, b01.y, b23.x, b23.y, b45.x, b45.y};
            unsigned long long bd[6];
            #pragma unroll
            for (int j = 0; j < 6; j++) {
                unsigned int u = __float_as_uint(bv[j]);
                PACK_F32X2(bd[j], u, u);
            }
            #pragma unroll
            for (int p = 0; p < 2; p++)
                #pragma unroll
                for (int j = 0; j < 6; j++)
                    FMA_F32X2(acc2[p][j], a2[p], bd[j], acc2[p][j]);
        }
    }

    const float* bb = bias + (size_t)b * 96;
    float* gb = gi + (size_t)b * 6144;
    #pragma unroll
    for (int p = 0; p < 2; p++) {
        int gm0 = r0 + 2 * p;
        #pragma unroll
        for (int j = 0; j < 6; j++) {
            int gn = c0 + j;
            unsigned int ul, uh;
            UNPACK_F32X2(ul, uh, acc2[p][j]);
            float bv = bb[gn];
            gb[(size_t)gm0 * 96 + gn]       = __uint_as_float(ul) + bv;
            gb[(size_t)(gm0 + 1) * 96 + gn] = __uint_as_float(uh) + bv;
        }
    }
}

// ---------------- GRU (R14) ------------------------------------------------------
__device__ __forceinline__ float fsigm(float x) {
    return __fdividef(1.f, 1.f + __expf(-x));
}
__device__ __forceinline__ float ftanh(float x) {
    return 2.f * __fdividef(1.f, 1.f + __expf(-2.f * x)) - 1.f;
}
__device__ __forceinline__ float hsum2(unsigned long long a) {
    unsigned int lo, hi;
    UNPACK_F32X2(lo, hi, a);
    return __uint_as_float(lo) + __uint_as_float(hi);
}

__global__ void __launch_bounds__(64) gru_kernel(
    const float* __restrict__ giAll,
    const float* __restrict__ Whh0, const float* __restrict__ bhh0,
    const float* __restrict__ Wih1, const float* __restrict__ bih1,
    const float* __restrict__ Whh1, const float* __restrict__ bhh1,
    const float* __restrict__ Hpre,
    float* __restrict__ gruOut, float* __restrict__ outCatH)
{
    int n = blockIdx.x;
    int lane = threadIdx.x & 31;
    int w = threadIdx.x >> 5;

    __shared__ __align__(16) float h0buf[2][32];
    __shared__ __align__(16) float h0cur[32];
    __shared__ __align__(16) float h1s[32];

    if (w == 0) {
        unsigned long long wr2[16], wz2[16], wn2[16];
        {
            const float4* pr = (const float4*)(Whh0 + (size_t)n * 3072 + lane * 32);
            const float4* pz = (const float4*)(Whh0 + (size_t)n * 3072 + (32 + lane) * 32);
            const float4* pn = (const float4*)(Whh0 + (size_t)n * 3072 + (64 + lane) * 32);
            #pragma unroll
            for (int q = 0; q < 8; q++) {
                float4 a = pr[q], bq = pz[q], c = pn[q];
                PACK_F32X2(wr2[2*q],   __float_as_uint(a.x),  __float_as_uint(a.y));
                PACK_F32X2(wr2[2*q+1], __float_as_uint(a.z),  __float_as_uint(a.w));
                PACK_F32X2(wz2[2*q],   __float_as_uint(bq.x), __float_as_uint(bq.y));
                PACK_F32X2(wz2[2*q+1], __float_as_uint(bq.z), __float_as_uint(bq.w));
                PACK_F32X2(wn2[2*q],   __float_as_uint(c.x),  __float_as_uint(c.y));
                PACK_F32X2(wn2[2*q+1], __float_as_uint(c.z),  __float_as_uint(c.w));
            }
        }
        float bhr = bhh0[(size_t)n * 96 + lane];
        float bhz = bhh0[(size_t)n * 96 + 32 + lane];
        float bhn = bhh0[(size_t)n * 96 + 64 + lane];
        float h0 = Hpre[(size_t)n * 32 + lane];
        h0cur[lane] = h0;
        __syncwarp();

        const float* gin = giAll + (size_t)n * 6144;
        float gir = gin[lane], giz = gin[32 + lane], ginn = gin[64 + lane];

        for (int t = 0; t < SS; t++) {
            unsigned long long ar2 = 0ull, az2 = 0ull, an2 = 0ull;
            const ulonglong2* hp = (const ulonglong2*)h0cur;
            #pragma unroll
            for (int q = 0; q < 8; q++) {
                ulonglong2 hv = hp[q];
                FMA_F32X2(ar2, wr2[2*q],   hv.x, ar2);
                FMA_F32X2(az2, wz2[2*q],   hv.x, az2);
                FMA_F32X2(an2, wn2[2*q],   hv.x, an2);
                FMA_F32X2(ar2, wr2[2*q+1], hv.y, ar2);
                FMA_F32X2(az2, wz2[2*q+1], hv.y, az2);
                FMA_F32X2(an2, wn2[2*q+1], hv.y, an2);
            }
            float r = fsigm(gir + bhr + hsum2(ar2));
            float z = fsigm(giz + bhz + hsum2(az2));
            float nn = ftanh(ginn + r * (bhn + hsum2(an2)));
            h0 = (1.f - z) * nn + z * h0;
            if (t + 1 < SS) {
                gir  = gin[(t + 1) * 96 + lane];
                giz  = gin[(t + 1) * 96 + 32 + lane];
                ginn = gin[(t + 1) * 96 + 64 + lane];
            }
            __syncwarp();
            h0cur[lane] = h0;
            h0buf[t & 1][lane] = h0;
            __syncwarp();
            __syncthreads();
        }
        outCatH[(size_t)n * 32 + lane] = h0;
    } else {
        unsigned long long vr2[16], vz2[16], vn2[16], ur2[16], uz2[16], un2[16];
        {
            const float4* p0 = (const float4*)(Wih1 + (size_t)n * 3072 + lane * 32);
            const float4* p1 = (const float4*)(Wih1 + (size_t)n * 3072 + (32 + lane) * 32);
            const float4* p2 = (const float4*)(Wih1 + (size_t)n * 3072 + (64 + lane) * 32);
            const float4* p3 = (const float4*)(Whh1 + (size_t)n * 3072 + lane * 32);
            const float4* p4 = (const float4*)(Whh1 + (size_t)n * 3072 + (32 + lane) * 32);
            const float4* p5 = (const float4*)(Whh1 + (size_t)n * 3072 + (64 + lane) * 32);
            #pragma unroll
            for (int q = 0; q < 8; q++) {
                float4 a = p0[q], bq = p1[q], c = p2[q], d = p3[q], e = p4[q], f = p5[q];
                PACK_F32X2(vr2[2*q],   __float_as_uint(a.x),  __float_as_uint(a.y));
                PACK_F32X2(vr2[2*q+1], __float_as_uint(a.z),  __float_as_uint(a.w));
                PACK_F32X2(vz2[2*q],   __float_as_uint(bq.x), __float_as_uint(bq.y));
                PACK_F32X2(vz2[2*q+1], __float_as_uint(bq.z), __float_as_uint(bq.w));
                PACK_F32X2(vn2[2*q],   __float_as_uint(c.x),  __float_as_uint(c.y));
                PACK_F32X2(vn2[2*q+1], __float_as_uint(c.z),  __float_as_uint(c.w));
                PACK_F32X2(ur2[2*q],   __float_as_uint(d.x),  __float_as_uint(d.y));
                PACK_F32X2(ur2[2*q+1], __float_as_uint(d.z),  __float_as_uint(d.w));
                PACK_F32X2(uz2[2*q],   __float_as_uint(e.x),  __float_as_uint(e.y));
                PACK_F32X2(uz2[2*q+1], __float_as_uint(e.z),  __float_as_uint(e.w));
                PACK_F32X2(un2[2*q],   __float_as_uint(f.x),  __float_as_uint(f.y));
                PACK_F32X2(un2[2*q+1], __float_as_uint(f.z),  __float_as_uint(f.w));
            }
        }
        float bir = bih1[(size_t)n * 96 + lane];
        float biz = bih1[(size_t)n * 96 + 32 + lane];
        float bin = bih1[(size_t)n * 96 + 64 + lane];
        float bhr = bhh1[(size_t)n * 96 + lane];
        float bhz = bhh1[(size_t)n * 96 + 32 + lane];
        float bhn = bhh1[(size_t)n * 96 + 64 + lane];
        float h1 = Hpre[8192 + (size_t)n * 32 + lane];
        h1s[lane] = h1;
        __syncwarp();

        float* outp = gruOut + (size_t)n * SS * 32 + lane;

        for (int t = 0; t < SS; t++) {
            __syncthreads();
            const ulonglong2* xp = (const ulonglong2*)h0buf[t & 1];
            const ulonglong2* hp = (const ulonglong2*)h1s;
            unsigned long long ar2 = 0ull, az2 = 0ull, an2 = 0ull;
            unsigned long long cr2 = 0ull, cz2 = 0ull, cn2 = 0ull;
            #pragma unroll
            for (int q = 0; q < 8; q++) {
                ulonglong2 xv = xp[q];
                ulonglong2 hv = hp[q];
                FMA_F32X2(ar2, vr2[2*q],   xv.x, ar2);
                FMA_F32X2(az2, vz2[2*q],   xv.x, az2);
                FMA_F32X2(an2, vn2[2*q],   xv.x, an2);
                FMA_F32X2(cr2, ur2[2*q],   hv.x, cr2);
                FMA_F32X2(cz2, uz2[2*q],   hv.x, cz2);
                FMA_F32X2(cn2, un2[2*q],   hv.x, cn2);
                FMA_F32X2(ar2, vr2[2*q+1], xv.y, ar2);
                FMA_F32X2(az2, vz2[2*q+1], xv.y, az2);
                FMA_F32X2(an2, vn2[2*q+1], xv.y, an2);
                FMA_F32X2(cr2, ur2[2*q+1], hv.y, cr2);
                FMA_F32X2(cz2, uz2[2*q+1], hv.y, cz2);
                FMA_F32X2(cn2, un2[2*q+1], hv.y, cn2);
            }
            float r = fsigm(bir + bhr + hsum2(ar2) + hsum2(cr2));
            float z = fsigm(biz + bhz + hsum2(az2) + hsum2(cz2));
            float nn = ftanh(bin + hsum2(an2) + r * (bhn + hsum2(cn2)));
            h1 = (1.f - z) * nn + z * h1;
            __syncwarp();
            h1s[lane] = h1;
            __syncwarp();
            outp[t * 32] = h1;
        }
        outCatH[8192 + (size_t)n * 32 + lane] = h1;
    }
}

// ---------------- fused fc1+fc2+fc3 (unchanged) --------------------------------
__global__ void fc_fused(const float* __restrict__ gru,
                         const float* __restrict__ W1, const float* __restrict__ b1,
                         const float* __restrict__ W2, const float* __restrict__ b2,
                         const float* __restrict__ w3, const float* __restrict__ b3,
                         float* __restrict__ ct)
{
    int n = blockIdx.x;
    int tid = threadIdx.x;
    int warp = tid >> 5, lane = tid & 31;
    __shared__ float W1s[32 * 33], W2s[32 * 33];
    __shared__ float w3s[32], b1s[32], b2s[32];
    __shared__ float xs[8][33];

    for (int idx = tid; idx < 1024; idx += 256) {
        int r = idx >> 5, c = idx & 31;
        W1s[r * 33 + c] = W1[(size_t)n * 1024 + idx];
        W2s[r * 33 + c] = W2[(size_t)n * 1024 + idx];
    }
    if (tid < 32) {
        w3s[tid] = w3[(size_t)n * 32 + tid];
        b1s[tid] = b1[(size_t)n * 32 + tid];
        b2s[tid] = b2[(size_t)n * 32 + tid];
    }
    __syncthreads();
    float b3v = b3[n];

    for (int s = warp; s < 64; s += 8) {
        float xv = gru[((size_t)n * 64 + s) * 32 + lane];
        xs[warp][lane] = xv;
        __syncwarp();
        float h1 = b1s[lane];
        #pragma unroll
        for (int j = 0; j < 32; j++) h1 += W1s[lane * 33 + j] * xs[warp][j];
        h1 = fmaxf(h1, 0.f);
        __syncwarp();
        xs[warp][lane] = h1;
        __syncwarp();
        float h2 = b2s[lane];
        #pragma unroll
        for (int j = 0; j < 32; j++) h2 += W2s[lane * 33 + j] * xs[warp][j];
        h2 = fmaxf(h2, 0.f);
        float p = h2 * w3s[lane];
        #pragma unroll
        for (int o = 16; o; o >>= 1) p += __shfl_xor_sync(0xffffffffu, p, o);
        if (lane == 0) ct[(size_t)n * 64 + s] = p + b3v;
        __syncwarp();
    }
}

// ---------------- whole-GAT-per-block output stage (unchanged) ------------------
__global__ void __launch_bounds__(1024) out_gat(
    const float* __restrict__ inp, int inStride, int Kd,
    const float* __restrict__ W0, const float* __restrict__ a0,
    const float* __restrict__ W1, const float* __restrict__ a1,
    const float* __restrict__ adj,
    float* __restrict__ outp, int outRowStride)
{
    const float* Wm = (blockIdx.y == 0) ? W0 : W1;
    const float* av = (blockIdx.y == 0) ? a0 : a1;
    int dstOff = blockIdx.y * 64;
    int mBase = blockIdx.x * 32;

    extern __shared__ float sm[];
    float* WhS = sm;
    float* WS  = WhS + 256 * 65;
    float* ctC = WS + 64 * (Kd + 4);
    float* aS  = ctC + 64 * Kd;
    float* e1  = aS + 128;
    float* e1p = e1 + 256;
    float* e2  = e1p + 256;
    float* e2p = e2 + 256;
    float* f1  = e2p + 256;
    float* f2  = f1 + 256;
    float* pb  = f2 + 256;

    int tid = threadIdx.x;
    for (int i = tid; i < 64 * Kd; i += 1024) {
        int g = i / Kd, k = i % Kd;
        WS[g * (Kd + 4) + k] = Wm[(size_t)k * 64 + g];
    }
    if (tid < 128) aS[tid] = av[tid];

    int g = tid & 63, mq = tid >> 6;
    for (int ch = 0; ch < 4; ch++) {
        __syncthreads();
        for (int i = tid; i < 64 * Kd; i += 1024)
            ctC[i] = inp[(size_t)(ch * 64 + i / Kd) * inStride + (i % Kd)];
        __syncthreads();
        float acc[4] = {0.f, 0.f, 0.f, 0.f};
        for (int k = 0; k < Kd; k += 4) {
            float4 wv = *(const float4*)&WS[g * (Kd + 4) + k];
            #pragma unroll
            for (int rr = 0; rr < 4; rr++) {
                float4 cv = *(const float4*)&ctC[(mq * 4 + rr) * Kd + k];
                acc[rr] += cv.x * wv.x + cv.y * wv.y + cv.z * wv.z + cv.w * wv.w;
            }
        }
        #pragma unroll
        for (int rr = 0; rr < 4; rr++)
            WhS[(ch * 64 + mq * 4 + rr) * 65 + g] = acc[rr];
    }
    __syncthreads();
    if (tid < 256) {
        float s1 = 0.f, s2 = 0.f;
        #pragma unroll
        for (int c = 0; c < 64; c++) {
            float w = WhS[tid * 65 + c];
            s1 += w * aS[c];
            s2 += w * aS[64 + c];
        }
        f1[tid] = s1; f2[tid] = s2;
        e1[tid] = __expf(s1); e1p[tid] = __expf(0.2f * s1);
        e2[tid] = __expf(s2); e2p[tid] = __expf(0.2f * s2);
    }
    __syncthreads();

    int w = tid >> 5, lane = tid & 31;
    {
        int m = mBase + w;
        const float* adjrow = adj + (size_t)m * 256;
        float f1m = f1[m], E1m = e1[m], E1pm = e1p[m];
        float s = 0.f;
        for (int k = lane; k < 256; k += 32) {
            float f = f1m + f2[k];
            float p = (f >= 0.f) ? E1m * e2[k] : E1pm * e2p[k];
            p = (adjrow[k] > 0.f) ? p : 0.f;
            pb[w * 256 + k] = p;
            s += p;
        }
        #pragma unroll
        for (int o = 16; o; o >>= 1) s += __shfl_xor_sync(0xffffffffu, s, o);
        float inv = 1.f / s;
        __syncwarp();
        #pragma unroll
        for (int c0 = 0; c0 < 64; c0 += 32) {
            int c = c0 + lane;
            float acc0 = 0.f, acc1 = 0.f;
            for (int k = 0; k < 256; k += 4) {
                float4 p4 = *(const float4*)&pb[w * 256 + k];
                acc0 += p4.x * WhS[(k + 0) * 65 + c] + p4.z * WhS[(k + 2) * 65 + c];
                acc1 += p4.y * WhS[(k + 1) * 65 + c] + p4.w * WhS[(k + 3) * 65 + c];
            }
            outp[(size_t)m * outRowStride + dstOff + c] = (acc0 + acc1) * inv;
        }
    }
}

// ---------------- launch -------------------------------------------------------
extern "C" void kernel_launch(void* const* d_in, const int* in_sizes, int n_in,
                              void* d_out, int out_size)
{
    const float* x     = (const float*)d_in[0];
    const float* Fadj  = (const float*)d_in[1];
    const float* Tadj  = (const float*)d_in[2];
    const float* adj   = (const float*)d_in[3];
    const float* Hpre  = (const float*)d_in[4];
    const float* FattW = (const float*)d_in[5];
    const float* Fatta = (const float*)d_in[6];
    const float* TattW = (const float*)d_in[7];
    const float* Tatta = (const float*)d_in[8];
    const float* Wih0  = (const float*)d_in[9];
    const float* Whh0  = (const float*)d_in[10];
    const float* bih0  = (const float*)d_in[11];
    const float* bhh0  = (const float*)d_in[12];
    const float* Wih1  = (const float*)d_in[13];
    const float* Whh1  = (const float*)d_in[14];
    const float* bih1  = (const float*)d_in[15];
    const float* bhh1  = (const float*)d_in[16];
    const float* fc1w  = (const float*)d_in[17];
    const float* fc1b  = (const float*)d_in[18];
    const float* fc2w  = (const float*)d_in[19];
    const float* fc2b  = (const float*)d_in[20];
    const float* fc3w  = (const float*)d_in[21];
    const float* fc3b  = (const float*)d_in[22];
    const float* oW    = (const float*)d_in[23];
    const float* oa    = (const float*)d_in[24];
    const float* o1W   = (const float*)d_in[25];
    const float* o1a   = (const float*)d_in[26];
    const float* o2W   = (const float*)d_in[27];
    const float* o2a   = (const float*)d_in[28];
    float* out = (float*)d_out;

    float *WhF, *WhT, *Tat, *Fat, *gi, *gru, *ct, *cat2, *Fb;
    cudaGetSymbolAddress((void**)&WhF,  g_WhF);
    cudaGetSymbolAddress((void**)&WhT,  g_WhT);
    cudaGetSymbolAddress((void**)&Tat,  g_Tat);
    cudaGetSymbolAddress((void**)&Fat,  g_Fat);
    cudaGetSymbolAddress((void**)&gi,   g_gi);
    cudaGetSymbolAddress((void**)&gru,  g_gru);
    cudaGetSymbolAddress((void**)&ct,   g_ct);
    cudaGetSymbolAddress((void**)&cat2, g_cat2);
    cudaGetSymbolAddress((void**)&Fb,   g_F);
    float* F1F = Fb;
    float* F2F = Fb + NN * WWIN;
    float* F1T = Fb + 2 * NN * WWIN;
    float* F2T = Fb + 3 * NN * WWIN;

    cudaFuncSetAttribute(out_gat, cudaFuncAttributeMaxDynamicSharedMemorySize, 180224);

    // 1. zero f1/f2 accumulators
    cudaMemsetAsync(Fb, 0, 4 * NN * WWIN * sizeof(float));

    // 2. both Wh GEMMs (Feature + Time), compact grid
    gemm_wh_both<<<dim3(1, 1, 1024), 256>>>(x, FattW, Fatta, TattW, Tatta,
                                            WhF, WhT, F1F, F2F, F1T, F2T);

    // 3. both softmax+PV, compact grid
    gat_pv_both<<<dim3(1, 1, 1024), 256>>>(F1F, F2F, Fadj, WhF, Fat,
                                           F1T, F2T, Tadj, WhT, Tat);

    // 4. gi = [Fat | Tat^T | x] @ Wih0^T + bih0
    gi_gemm<<<256, 256>>>(Fat, Tat, x, Wih0, bih0, gi);

    // 5. GRU recurrence (cat_H -> d_out[16384:])
    gru_kernel<<<256, 64>>>(gi, Whh0, bhh0, Wih1, bih1, Whh1, bhh1, Hpre,
                            gru, out + 16384);

    // 6. FC stack -> ct
    fc_fused<<<256, 256>>>(gru, fc1w, fc1b, fc2w, fc2b, fc3w, fc3b, ct);

    // 7. output GATs out/out1 -> cat2
    {
        size_t smem = (256*65 + 64*68 + 64*64 + 128 + 6*256 + 32*256) * sizeof(float);
        out_gat<<<dim3(8, 2), 1024, smem>>>(ct, 64, 64, oW, oa, o1W, o1a,
                                            adj, cat2, 128);
    }
    // 8. final GAT -> d_out[0:16384]
    {
        size_t smem = (256*65 + 64*132 + 64*128 + 128 + 6*256 + 32*256) * sizeof(float);
        out_gat<<<dim3(8, 1), 1024, smem>>>(cat2, 128, 128, o2W, o2a, o2W, o2a,
                                            adj, out, 64);
    }
}

// round 17
// speedup vs baseline: 1.0768x; 1.0252x over previous
#include <cuda_runtime.h>
#include <math.h>

#define NN 256
#define SS 64
#define WWIN 256
#define HH 32

// ---------------- scratch ------------------------------------------------------
__device__ float g_WhF[NN*SS*WWIN];
__device__ float g_WhT[NN*WWIN*SS];
__device__ float g_Tat[NN*WWIN*SS];
__device__ float g_Fat[NN*SS*WWIN];
__device__ float g_gi[NN*SS*96];
__device__ float g_gru[NN*SS*HH];
__device__ float g_ct[NN*SS];
__device__ float g_cat2[NN*2*SS];
__device__ float g_F[4*NN*WWIN];       // F1F | F2F | F1T | F2T

#define FMA_F32X2(d, a, b, c) \
    asm("fma.rn.f32x2 %0, %1, %2, %3;" : "=l"(d) : "l"(a), "l"(b), "l"(c))
#define PACK_F32X2(out, lo, hi) \
    asm("mov.b64 %0, {%1, %2};" : "=l"(out) : "r"(lo), "r"(hi))
#define UNPACK_F32X2(lo, hi, in) \
    asm("mov.b64 {%0, %1}, %2;" : "=r"(lo), "=r"(hi) : "l"(in))

// ---------------- gemm_wh impl (device) ----------------------------------------
template<int BM, int BN>
__device__ __forceinline__ void gemm_wh_impl(
    float* smem, int b, int bx, int by,
    const float* __restrict__ A, const float* __restrict__ B,
    float* __restrict__ C,
    int M, int N, int K,
    long long sAb, int sAm, int sAk,
    long long sBb, int sBk, int sBn,
    long long sCb, int sCm,
    const float* __restrict__ avec, long long aStride,
    float* __restrict__ F1o, float* __restrict__ F2o)
{
    constexpr int TX = BN / 8;
    constexpr int LA = BM * 16 / 256;
    constexpr int LB = BN * 16 / 256;

    int m0 = by * BM;
    int n0 = bx * BN;
    const float* Ab = A + (size_t)b * sAb;
    const float* Bb = B + (size_t)b * sBb;
    float*       Cb = C + (size_t)b * sCb;

    float (*As)[BM] = (float(*)[BM])smem;
    float (*Bs)[BN] = (float(*)[BN])(smem + 16 * BM);

    int tid = threadIdx.x;
    int tx = tid % TX, ty = tid / TX;
    int r0  = ty * 4;
    int c0a = tx * 4;
    int c0b = BN / 2 + tx * 4;
    bool aK1 = (sAk == 1);

    unsigned long long acc2[2][8];
    #pragma unroll
    for (int p = 0; p < 2; p++)
        #pragma unroll
        for (int j = 0; j < 8; j++) acc2[p][j] = 0ull;

    auto loadA = [&](int k0, float r[LA]) {
        if (aK1) {
            #pragma unroll
            for (int l = 0; l < LA; l++) {
                int e = tid + l * 256; int m = e >> 4, kk = e & 15;
                r[l] = Ab[(size_t)(m0 + m) * sAm + (k0 + kk)];
            }
        } else {
            #pragma unroll
            for (int l = 0; l < LA; l++) {
                int e = tid + l * 256; int m = e % BM, kk = e / BM;
                r[l] = Ab[(size_t)(m0 + m) + (size_t)(k0 + kk) * sAk];
            }
        }
    };
    auto storeA = [&](float r[LA]) {
        if (aK1) {
            #pragma unroll
            for (int l = 0; l < LA; l++) { int e = tid + l * 256; As[e & 15][e >> 4] = r[l]; }
        } else {
            #pragma unroll
            for (int l = 0; l < LA; l++) { int e = tid + l * 256; As[e / BM][e % BM] = r[l]; }
        }
    };
    auto loadB = [&](int k0, float r[LB]) {
        #pragma unroll
        for (int l = 0; l < LB; l++) {
            int e = tid + l * 256; int n = e % BN, kk = e / BN; int gn = n0 + n;
            r[l] = Bb[(size_t)(k0 + kk) * sBk + (size_t)gn * sBn];
        }
    };
    auto storeB = [&](float r[LB]) {
        #pragma unroll
        for (int l = 0; l < LB; l++) { int e = tid + l * 256; Bs[e / BN][e % BN] = r[l]; }
    };

    float ra[LA], rb[LB], na[LA], nb[LB];
    loadA(0, ra); loadB(0, rb);

    for (int k0 = 0; k0 < K; k0 += 16) {
        storeA(ra); storeB(rb);
        __syncthreads();
        if (k0 + 16 < K) { loadA(k0 + 16, na); loadB(k0 + 16, nb); }
        #pragma unroll
        for (int kk = 0; kk < 16; kk++) {
            ulonglong2 a01 = *(const ulonglong2*)&As[kk][r0];
            unsigned long long a2[2] = {a01.x, a01.y};
            float4 bA = *(const float4*)&Bs[kk][c0a];
            float4 bB = *(const float4*)&Bs[kk][c0b];
            float bv[8] = {bA.x, bA.y, bA.z, bA.w, bB.x, bB.y, bB.z, bB.w};
            unsigned long long bd[8];
            #pragma unroll
            for (int j = 0; j < 8; j++) {
                unsigned int u = __float_as_uint(bv[j]);
                PACK_F32X2(bd[j], u, u);
            }
            #pragma unroll
            for (int p = 0; p < 2; p++)
                #pragma unroll
                for (int j = 0; j < 8; j++)
                    FMA_F32X2(acc2[p][j], a2[p], bd[j], acc2[p][j]);
        }
        __syncthreads();
        #pragma unroll
        for (int l = 0; l < LA; l++) ra[l] = na[l];
        #pragma unroll
        for (int l = 0; l < LB; l++) rb[l] = nb[l];
    }

    #pragma unroll
    for (int p = 0; p < 2; p++) {
        int gm0 = m0 + r0 + 2 * p;
        #pragma unroll
        for (int j = 0; j < 8; j++) {
            int gn = n0 + ((j < 4) ? (c0a + j) : (c0b + j - 4));
            unsigned int ul, uh;
            UNPACK_F32X2(ul, uh, acc2[p][j]);
            Cb[(size_t)gm0 * sCm + gn]       = __uint_as_float(ul);
            Cb[(size_t)(gm0 + 1) * sCm + gn] = __uint_as_float(uh);
        }
    }
    {
        const float* ab = avec + (size_t)b * aStride;
        float a1v[8], a2v[8];
        #pragma unroll
        for (int j = 0; j < 8; j++) {
            int gn = n0 + ((j < 4) ? (c0a + j) : (c0b + j - 4));
            a1v[j] = ab[gn];
            a2v[j] = ab[N + gn];
        }
        #pragma unroll
        for (int p = 0; p < 2; p++) {
            float s1l = 0.f, s1h = 0.f, s2l = 0.f, s2h = 0.f;
            #pragma unroll
            for (int j = 0; j < 8; j++) {
                unsigned int ul, uh;
                UNPACK_F32X2(ul, uh, acc2[p][j]);
                float v0 = __uint_as_float(ul), v1 = __uint_as_float(uh);
                s1l += v0 * a1v[j]; s1h += v1 * a1v[j];
                s2l += v0 * a2v[j]; s2h += v1 * a2v[j];
            }
            #pragma unroll
            for (int o = TX >> 1; o; o >>= 1) {
                s1l += __shfl_xor_sync(0xffffffffu, s1l, o);
                s1h += __shfl_xor_sync(0xffffffffu, s1h, o);
                s2l += __shfl_xor_sync(0xffffffffu, s2l, o);
                s2h += __shfl_xor_sync(0xffffffffu, s2h, o);
            }
            if (tx == 0) {
                int gm0 = m0 + r0 + 2 * p;
                atomicAdd(&F1o[(size_t)b * M + gm0],     s1l);
                atomicAdd(&F1o[(size_t)b * M + gm0 + 1], s1h);
                atomicAdd(&F2o[(size_t)b * M + gm0],     s2l);
                atomicAdd(&F2o[(size_t)b * M + gm0 + 1], s2h);
            }
        }
    }
}

// compact grid: z in [0,1024).
__global__ void __launch_bounds__(256, 2) gemm_wh_both(
    const float* __restrict__ x,
    const float* __restrict__ FattW, const float* __restrict__ Fatta,
    const float* __restrict__ TattW, const float* __restrict__ Tatta,
    float* __restrict__ WhF, float* __restrict__ WhT,
    float* __restrict__ F1F, float* __restrict__ F2F,
    float* __restrict__ F1T, float* __restrict__ F2T)
{
    __shared__ float smem[16 * 64 + 16 * 128];
    int idx = blockIdx.z;
    if (idx < 512) {
        gemm_wh_impl<64,128>(smem, idx >> 1, idx & 1, 0,
            x, FattW, WhF, 64, 256, 256,
            16384LL, 256, 1,  65536LL, 256, 1,  16384LL, 256,
            Fatta, 512LL, F1F, F2F);
    } else {
        int j = idx - 512;
        gemm_wh_impl<128,64>(smem, j >> 1, 0, j & 1,
            x, TattW, WhT, 256, 64, 64,
            16384LL, 1, 256,  4096LL, 64, 1,  16384LL, 64,
            Tatta, 128LL, F1T, F2T);
    }
}

// ---------------- gat_pv impl: broadcast-A tiles (TX=32) ------------------------
// per-thread 2*RP rows x CN cols; TX = BN/CN = 32 -> all lanes share ty, so Pt
// reads are warp-broadcast (free). Bt reads are conflict-free float2 phases.
template<int BM, int BN, int RP, int CN>
__device__ __forceinline__ void gat_pv_impl(
    float* buf, int b, int bx, int by,
    const float* __restrict__ F1, const float* __restrict__ F2,
    const float* __restrict__ adj, long long adjBStride,
    const float* __restrict__ V, long long sVb, int sVm,
    int M,
    float* __restrict__ C, long long sCb, int sCm)
{
    constexpr int PS = BM + 8;
    constexpr int G  = 256 / BM;
    constexpr int KP = 32 / G;
    constexpr int TX = BN / CN;
    int m0 = by * BM;
    int n0 = bx * BN;

    float* f1s  = buf;
    float* Ae   = buf + BM;
    float* Ape  = buf + 2 * BM;
    float* rsum = buf + 3 * BM;
    float* f2s  = buf + 4 * BM;
    float* Bks  = f2s + 32;
    float* Bkps = f2s + 64;
    float* rs   = f2s + 96;
    float* Pt   = rs + 256;
    float* Bt   = Pt + 32 * PS;
    float* adjS = Bt + 32 * BN;

    int tid = threadIdx.x;
    int tx = tid % TX, ty = tid / TX;
    int r0 = ty * 2 * RP, c0 = tx * CN;

    size_t base = (size_t)b * M;
    if (tid < BM) {
        float f = F1[base + m0 + tid];
        f1s[tid] = f;
        Ae[tid]  = __expf(f);
        Ape[tid] = __expf(0.2f * f);
        rsum[tid] = 0.f;
    }

    const float* adjb = adj + (size_t)b * adjBStride;
    const float* Vb   = V + (size_t)b * sVb;

    unsigned long long acc2[RP][CN];
    #pragma unroll
    for (int p = 0; p < RP; p++)
        #pragma unroll
        for (int j = 0; j < CN; j++) acc2[p][j] = 0ull;

    int mP = tid % BM;
    int kg = tid / BM;

    for (int k0 = 0; k0 < M; k0 += 32) {
        __syncthreads();
        if (tid < 32) {
            float f = F2[base + k0 + tid];
            f2s[tid]  = f;
            Bks[tid]  = __expf(f);
            Bkps[tid] = __expf(0.2f * f);
        }
        #pragma unroll
        for (int l = 0; l < 32 * BN / 256; l++) {
            int e = tid + l * 256;
            int n = e % BN, kk = e / BN;
            Bt[kk * BN + n] = Vb[(size_t)(k0 + kk) * sVm + n0 + n];
        }
        #pragma unroll
        for (int l = 0; l < BM * 32 / 256; l++) {
            int e = tid + l * 256;
            int m = e >> 5, kk = e & 31;
            adjS[m * 33 + kk] = adjb[(size_t)(m0 + m) * M + k0 + kk];
        }
        __syncthreads();
        float part = 0.f;
        {
            float f1m = f1s[mP], Em = Ae[mP], Epm = Ape[mP];
            #pragma unroll
            for (int l = 0; l < KP; l++) {
                int kk = kg * KP + l;
                float av = adjS[mP * 33 + kk];
                float f = f1m + f2s[kk];
                float p = (f >= 0.f) ? Em * Bks[kk] : Epm * Bkps[kk];
                p = (av > 0.f) ? p : 0.f;
                Pt[kk * PS + mP] = p;
                part += p;
            }
        }
        rs[tid] = part;
        __syncthreads();
        if (tid < BM) {
            float s = 0.f;
            #pragma unroll
            for (int g = 0; g < G; g++) s += rs[g * BM + tid];
            rsum[tid] += s;
        }
        #pragma unroll
        for (int kk = 0; kk < 32; kk++) {
            unsigned long long a2[RP];
            #pragma unroll
            for (int q = 0; q < RP / 2; q++) {
                ulonglong2 aa = *(const ulonglong2*)&Pt[kk * PS + r0 + q * 4];
                a2[2 * q] = aa.x; a2[2 * q + 1] = aa.y;
            }
            float bv[CN];
            #pragma unroll
            for (int q = 0; q < CN / 2; q++) {
                float2 b2 = *(const float2*)&Bt[kk * BN + c0 + q * 2];
                bv[2 * q] = b2.x; bv[2 * q + 1] = b2.y;
            }
            unsigned long long bd[CN];
            #pragma unroll
            for (int j = 0; j < CN; j++) {
                unsigned int u = __float_as_uint(bv[j]);
                PACK_F32X2(bd[j], u, u);
            }
            #pragma unroll
            for (int p = 0; p < RP; p++)
                #pragma unroll
                for (int j = 0; j < CN; j++)
                    FMA_F32X2(acc2[p][j], a2[p], bd[j], acc2[p][j]);
        }
    }
    __syncthreads();

    float* Cb = C + (size_t)b * sCb;
    #pragma unroll
    for (int p = 0; p < RP; p++) {
        int gm0 = m0 + r0 + 2 * p;
        float inv0 = 1.f / rsum[r0 + 2 * p];
        float inv1 = 1.f / rsum[r0 + 2 * p + 1];
        #pragma unroll
        for (int j = 0; j < CN; j++) {
            int gn = n0 + c0 + j;
            unsigned int ul, uh;
            UNPACK_F32X2(ul, uh, acc2[p][j]);
            Cb[(size_t)gm0 * sCm + gn]       = __uint_as_float(ul) * inv0;
            Cb[(size_t)(gm0 + 1) * sCm + gn] = __uint_as_float(uh) * inv1;
        }
    }
}

__global__ void __launch_bounds__(256) gat_pv_both(
    const float* __restrict__ F1F, const float* __restrict__ F2F,
    const float* __restrict__ Fadj, const float* __restrict__ WhF,
    float* __restrict__ Fat,
    const float* __restrict__ F1T, const float* __restrict__ F2T,
    const float* __restrict__ Tadj, const float* __restrict__ WhT,
    float* __restrict__ Tat)
{
    __shared__ __align__(16) float buf[4*128 + 96 + 256 + 32*136 + 32*64 + 128*33];
    int idx = blockIdx.z;
    if (idx < 512) {
        gat_pv_impl<64,128,4,4>(buf, idx >> 1, idx & 1, 0,
            F1F, F2F, Fadj, 4096LL, WhF, 16384LL, 256, 64,
            Fat, 16384LL, 256);
    } else {
        int j = idx - 512;
        gat_pv_impl<128,64,8,2>(buf, j >> 1, 0, j & 1,
            F1T, F2T, Tadj, 65536LL, WhT, 16384LL, 64, 256,
            Tat, 16384LL, 64);
    }
}

// ---------------- gi GEMM v2 (R14) ---------------------------------------------
__global__ void __launch_bounds__(256) gi_gemm(
    const float* __restrict__ Fat, const float* __restrict__ Tat,
    const float* __restrict__ x,  const float* __restrict__ W,
    const float* __restrict__ bias, float* __restrict__ gi)
{
    int b = blockIdx.x;

    __shared__ float As[32 * 68];
    __shared__ float Bs[32 * 98];

    int tid = threadIdx.x;
    int tx = tid & 15, ty = tid >> 4;
    int r0 = ty * 4, c0 = tx * 6;

    const float* Wb = W + (size_t)b * 73728;

    unsigned long long acc2[2][6];
    #pragma unroll
    for (int p = 0; p < 2; p++)
        #pragma unroll
        for (int j = 0; j < 6; j++) acc2[p][j] = 0ull;

    for (int t = 0; t < 24; t++) {
        int k0 = t * 32;
        __syncthreads();
        if (k0 < 256 || k0 >= 512) {
            const float* S = (k0 < 256) ? (Fat + (size_t)b * 16384)
                                        : (x   + (size_t)b * 16384);
            int kb = (k0 < 256) ? k0 : (k0 - 512);
            #pragma unroll
            for (int l = 0; l < 2; l++) {
                int e = tid + l * 256;
                int m = e >> 3, kq = e & 7;
                float4 v = *(const float4*)&S[(size_t)m * 256 + kb + kq * 4];
                As[(kq * 4 + 0) * 68 + m] = v.x;
                As[(kq * 4 + 1) * 68 + m] = v.y;
                As[(kq * 4 + 2) * 68 + m] = v.z;
                As[(kq * 4 + 3) * 68 + m] = v.w;
            }
        } else {
            const float* S = Tat + (size_t)b * 16384;
            int kb = k0 - 256;
            #pragma unroll
            for (int l = 0; l < 8; l++) {
                int e = tid + l * 256;
                int m = e & 63, kk = e >> 6;
                As[kk * 68 + m] = S[(size_t)(kb + kk) * 64 + m];
            }
        }
        #pragma unroll
        for (int l = 0; l < 6; l++) {
            int e = tid + l * 256;
            int g = e >> 4, kp = e & 15;
            float2 v = *(const float2*)&Wb[(size_t)g * 768 + k0 + kp * 2];
            Bs[(kp * 2 + 0) * 98 + g] = v.x;
            Bs[(kp * 2 + 1) * 98 + g] = v.y;
        }
        __syncthreads();
        #pragma unroll
        for (int kk = 0; kk < 32; kk++) {
            ulonglong2 aa = *(const ulonglong2*)&As[kk * 68 + r0];
            unsigned long long a2[2] = {aa.x, aa.y};
            float2 b01 = *(const float2*)&Bs[kk * 98 + c0];
            float2 b23 = *(const float2*)&Bs[kk * 98 + c0 + 2];
            float2 b45 = *(const float2*)&Bs[kk * 98 + c0 + 4];
            float bv[6] = {b01.x, b01.y, b23.x, b23.y, b45.x, b45.y};
            unsigned long long bd[6];
            #pragma unroll
            for (int j = 0; j < 6; j++) {
                unsigned int u = __float_as_uint(bv[j]);
                PACK_F32X2(bd[j], u, u);
            }
            #pragma unroll
            for (int p = 0; p < 2; p++)
                #pragma unroll
                for (int j = 0; j < 6; j++)
                    FMA_F32X2(acc2[p][j], a2[p], bd[j], acc2[p][j]);
        }
    }

    const float* bb = bias + (size_t)b * 96;
    float* gb = gi + (size_t)b * 6144;
    #pragma unroll
    for (int p = 0; p < 2; p++) {
        int gm0 = r0 + 2 * p;
        #pragma unroll
        for (int j = 0; j < 6; j++) {
            int gn = c0 + j;
            unsigned int ul, uh;
            UNPACK_F32X2(ul, uh, acc2[p][j]);
            float bv = bb[gn];
            gb[(size_t)gm0 * 96 + gn]       = __uint_as_float(ul) + bv;
            gb[(size_t)(gm0 + 1) * 96 + gn] = __uint_as_float(uh) + bv;
        }
    }
}

// ---------------- GRU (R14) ------------------------------------------------------
__device__ __forceinline__ float fsigm(float x) {
    return __fdividef(1.f, 1.f + __expf(-x));
}
__device__ __forceinline__ float ftanh(float x) {
    return 2.f * __fdividef(1.f, 1.f + __expf(-2.f * x)) - 1.f;
}
__device__ __forceinline__ float hsum2(unsigned long long a) {
    unsigned int lo, hi;
    UNPACK_F32X2(lo, hi, a);
    return __uint_as_float(lo) + __uint_as_float(hi);
}

__global__ void __launch_bounds__(64) gru_kernel(
    const float* __restrict__ giAll,
    const float* __restrict__ Whh0, const float* __restrict__ bhh0,
    const float* __restrict__ Wih1, const float* __restrict__ bih1,
    const float* __restrict__ Whh1, const float* __restrict__ bhh1,
    const float* __restrict__ Hpre,
    float* __restrict__ gruOut, float* __restrict__ outCatH)
{
    int n = blockIdx.x;
    int lane = threadIdx.x & 31;
    int w = threadIdx.x >> 5;

    __shared__ __align__(16) float h0buf[2][32];
    __shared__ __align__(16) float h0cur[32];
    __shared__ __align__(16) float h1s[32];

    if (w == 0) {
        unsigned long long wr2[16], wz2[16], wn2[16];
        {
            const float4* pr = (const float4*)(Whh0 + (size_t)n * 3072 + lane * 32);
            const float4* pz = (const float4*)(Whh0 + (size_t)n * 3072 + (32 + lane) * 32);
            const float4* pn = (const float4*)(Whh0 + (size_t)n * 3072 + (64 + lane) * 32);
            #pragma unroll
            for (int q = 0; q < 8; q++) {
                float4 a = pr[q], bq = pz[q], c = pn[q];
                PACK_F32X2(wr2[2*q],   __float_as_uint(a.x),  __float_as_uint(a.y));
                PACK_F32X2(wr2[2*q+1], __float_as_uint(a.z),  __float_as_uint(a.w));
                PACK_F32X2(wz2[2*q],   __float_as_uint(bq.x), __float_as_uint(bq.y));
                PACK_F32X2(wz2[2*q+1], __float_as_uint(bq.z), __float_as_uint(bq.w));
                PACK_F32X2(wn2[2*q],   __float_as_uint(c.x),  __float_as_uint(c.y));
                PACK_F32X2(wn2[2*q+1], __float_as_uint(c.z),  __float_as_uint(c.w));
            }
        }
        float bhr = bhh0[(size_t)n * 96 + lane];
        float bhz = bhh0[(size_t)n * 96 + 32 + lane];
        float bhn = bhh0[(size_t)n * 96 + 64 + lane];
        float h0 = Hpre[(size_t)n * 32 + lane];
        h0cur[lane] = h0;
        __syncwarp();

        const float* gin = giAll + (size_t)n * 6144;
        float gir = gin[lane], giz = gin[32 + lane], ginn = gin[64 + lane];

        for (int t = 0; t < SS; t++) {
            unsigned long long ar2 = 0ull, az2 = 0ull, an2 = 0ull;
            const ulonglong2* hp = (const ulonglong2*)h0cur;
            #pragma unroll
            for (int q = 0; q < 8; q++) {
                ulonglong2 hv = hp[q];
                FMA_F32X2(ar2, wr2[2*q],   hv.x, ar2);
                FMA_F32X2(az2, wz2[2*q],   hv.x, az2);
                FMA_F32X2(an2, wn2[2*q],   hv.x, an2);
                FMA_F32X2(ar2, wr2[2*q+1], hv.y, ar2);
                FMA_F32X2(az2, wz2[2*q+1], hv.y, az2);
                FMA_F32X2(an2, wn2[2*q+1], hv.y, an2);
            }
            float r = fsigm(gir + bhr + hsum2(ar2));
            float z = fsigm(giz + bhz + hsum2(az2));
            float nn = ftanh(ginn + r * (bhn + hsum2(an2)));
            h0 = (1.f - z) * nn + z * h0;
            if (t + 1 < SS) {
                gir  = gin[(t + 1) * 96 + lane];
                giz  = gin[(t + 1) * 96 + 32 + lane];
                ginn = gin[(t + 1) * 96 + 64 + lane];
            }
            __syncwarp();
            h0cur[lane] = h0;
            h0buf[t & 1][lane] = h0;
            __syncwarp();
            __syncthreads();
        }
        outCatH[(size_t)n * 32 + lane] = h0;
    } else {
        unsigned long long vr2[16], vz2[16], vn2[16], ur2[16], uz2[16], un2[16];
        {
            const float4* p0 = (const float4*)(Wih1 + (size_t)n * 3072 + lane * 32);
            const float4* p1 = (const float4*)(Wih1 + (size_t)n * 3072 + (32 + lane) * 32);
            const float4* p2 = (const float4*)(Wih1 + (size_t)n * 3072 + (64 + lane) * 32);
            const float4* p3 = (const float4*)(Whh1 + (size_t)n * 3072 + lane * 32);
            const float4* p4 = (const float4*)(Whh1 + (size_t)n * 3072 + (32 + lane) * 32);
            const float4* p5 = (const float4*)(Whh1 + (size_t)n * 3072 + (64 + lane) * 32);
            #pragma unroll
            for (int q = 0; q < 8; q++) {
                float4 a = p0[q], bq = p1[q], c = p2[q], d = p3[q], e = p4[q], f = p5[q];
                PACK_F32X2(vr2[2*q],   __float_as_uint(a.x),  __float_as_uint(a.y));
                PACK_F32X2(vr2[2*q+1], __float_as_uint(a.z),  __float_as_uint(a.w));
                PACK_F32X2(vz2[2*q],   __float_as_uint(bq.x), __float_as_uint(bq.y));
                PACK_F32X2(vz2[2*q+1], __float_as_uint(bq.z), __float_as_uint(bq.w));
                PACK_F32X2(vn2[2*q],   __float_as_uint(c.x),  __float_as_uint(c.y));
                PACK_F32X2(vn2[2*q+1], __float_as_uint(c.z),  __float_as_uint(c.w));
                PACK_F32X2(ur2[2*q],   __float_as_uint(d.x),  __float_as_uint(d.y));
                PACK_F32X2(ur2[2*q+1], __float_as_uint(d.z),  __float_as_uint(d.w));
                PACK_F32X2(uz2[2*q],   __float_as_uint(e.x),  __float_as_uint(e.y));
                PACK_F32X2(uz2[2*q+1], __float_as_uint(e.z),  __float_as_uint(e.w));
                PACK_F32X2(un2[2*q],   __float_as_uint(f.x),  __float_as_uint(f.y));
                PACK_F32X2(un2[2*q+1], __float_as_uint(f.z),  __float_as_uint(f.w));
            }
        }
        float bir = bih1[(size_t)n * 96 + lane];
        float biz = bih1[(size_t)n * 96 + 32 + lane];
        float bin = bih1[(size_t)n * 96 + 64 + lane];
        float bhr = bhh1[(size_t)n * 96 + lane];
        float bhz = bhh1[(size_t)n * 96 + 32 + lane];
        float bhn = bhh1[(size_t)n * 96 + 64 + lane];
        float h1 = Hpre[8192 + (size_t)n * 32 + lane];
        h1s[lane] = h1;
        __syncwarp();

        float* outp = gruOut + (size_t)n * SS * 32 + lane;

        for (int t = 0; t < SS; t++) {
            __syncthreads();
            const ulonglong2* xp = (const ulonglong2*)h0buf[t & 1];
            const ulonglong2* hp = (const ulonglong2*)h1s;
            unsigned long long ar2 = 0ull, az2 = 0ull, an2 = 0ull;
            unsigned long long cr2 = 0ull, cz2 = 0ull, cn2 = 0ull;
            #pragma unroll
            for (int q = 0; q < 8; q++) {
                ulonglong2 xv = xp[q];
                ulonglong2 hv = hp[q];
                FMA_F32X2(ar2, vr2[2*q],   xv.x, ar2);
                FMA_F32X2(az2, vz2[2*q],   xv.x, az2);
                FMA_F32X2(an2, vn2[2*q],   xv.x, an2);
                FMA_F32X2(cr2, ur2[2*q],   hv.x, cr2);
                FMA_F32X2(cz2, uz2[2*q],   hv.x, cz2);
                FMA_F32X2(cn2, un2[2*q],   hv.x, cn2);
                FMA_F32X2(ar2, vr2[2*q+1], xv.y, ar2);
                FMA_F32X2(az2, vz2[2*q+1], xv.y, az2);
                FMA_F32X2(an2, vn2[2*q+1], xv.y, an2);
                FMA_F32X2(cr2, ur2[2*q+1], hv.y, cr2);
                FMA_F32X2(cz2, uz2[2*q+1], hv.y, cz2);
                FMA_F32X2(cn2, un2[2*q+1], hv.y, cn2);
            }
            float r = fsigm(bir + bhr + hsum2(ar2) + hsum2(cr2));
            float z = fsigm(biz + bhz + hsum2(az2) + hsum2(cz2));
            float nn = ftanh(bin + hsum2(an2) + r * (bhn + hsum2(cn2)));
            h1 = (1.f - z) * nn + z * h1;
            __syncwarp();
            h1s[lane] = h1;
            __syncwarp();
            outp[t * 32] = h1;
        }
        outCatH[8192 + (size_t)n * 32 + lane] = h1;
    }
}

// ---------------- fused fc1+fc2+fc3 (unchanged) --------------------------------
__global__ void fc_fused(const float* __restrict__ gru,
                         const float* __restrict__ W1, const float* __restrict__ b1,
                         const float* __restrict__ W2, const float* __restrict__ b2,
                         const float* __restrict__ w3, const float* __restrict__ b3,
                         float* __restrict__ ct)
{
    int n = blockIdx.x;
    int tid = threadIdx.x;
    int warp = tid >> 5, lane = tid & 31;
    __shared__ float W1s[32 * 33], W2s[32 * 33];
    __shared__ float w3s[32], b1s[32], b2s[32];
    __shared__ float xs[8][33];

    for (int idx = tid; idx < 1024; idx += 256) {
        int r = idx >> 5, c = idx & 31;
        W1s[r * 33 + c] = W1[(size_t)n * 1024 + idx];
        W2s[r * 33 + c] = W2[(size_t)n * 1024 + idx];
    }
    if (tid < 32) {
        w3s[tid] = w3[(size_t)n * 32 + tid];
        b1s[tid] = b1[(size_t)n * 32 + tid];
        b2s[tid] = b2[(size_t)n * 32 + tid];
    }
    __syncthreads();
    float b3v = b3[n];

    for (int s = warp; s < 64; s += 8) {
        float xv = gru[((size_t)n * 64 + s) * 32 + lane];
        xs[warp][lane] = xv;
        __syncwarp();
        float h1 = b1s[lane];
        #pragma unroll
        for (int j = 0; j < 32; j++) h1 += W1s[lane * 33 + j] * xs[warp][j];
        h1 = fmaxf(h1, 0.f);
        __syncwarp();
        xs[warp][lane] = h1;
        __syncwarp();
        float h2 = b2s[lane];
        #pragma unroll
        for (int j = 0; j < 32; j++) h2 += W2s[lane * 33 + j] * xs[warp][j];
        h2 = fmaxf(h2, 0.f);
        float p = h2 * w3s[lane];
        #pragma unroll
        for (int o = 16; o; o >>= 1) p += __shfl_xor_sync(0xffffffffu, p, o);
        if (lane == 0) ct[(size_t)n * 64 + s] = p + b3v;
        __syncwarp();
    }
}

// ---------------- whole-GAT-per-block output stage (unchanged) ------------------
__global__ void __launch_bounds__(1024) out_gat(
    const float* __restrict__ inp, int inStride, int Kd,
    const float* __restrict__ W0, const float* __restrict__ a0,
    const float* __restrict__ W1, const float* __restrict__ a1,
    const float* __restrict__ adj,
    float* __restrict__ outp, int outRowStride)
{
    const float* Wm = (blockIdx.y == 0) ? W0 : W1;
    const float* av = (blockIdx.y == 0) ? a0 : a1;
    int dstOff = blockIdx.y * 64;
    int mBase = blockIdx.x * 32;

    extern __shared__ float sm[];
    float* WhS = sm;
    float* WS  = WhS + 256 * 65;
    float* ctC = WS + 64 * (Kd + 4);
    float* aS  = ctC + 64 * Kd;
    float* e1  = aS + 128;
    float* e1p = e1 + 256;
    float* e2  = e1p + 256;
    float* e2p = e2 + 256;
    float* f1  = e2p + 256;
    float* f2  = f1 + 256;
    float* pb  = f2 + 256;

    int tid = threadIdx.x;
    for (int i = tid; i < 64 * Kd; i += 1024) {
        int g = i / Kd, k = i % Kd;
        WS[g * (Kd + 4) + k] = Wm[(size_t)k * 64 + g];
    }
    if (tid < 128) aS[tid] = av[tid];

    int g = tid & 63, mq = tid >> 6;
    for (int ch = 0; ch < 4; ch++) {
        __syncthreads();
        for (int i = tid; i < 64 * Kd; i += 1024)
            ctC[i] = inp[(size_t)(ch * 64 + i / Kd) * inStride + (i % Kd)];
        __syncthreads();
        float acc[4] = {0.f, 0.f, 0.f, 0.f};
        for (int k = 0; k < Kd; k += 4) {
            float4 wv = *(const float4*)&WS[g * (Kd + 4) + k];
            #pragma unroll
            for (int rr = 0; rr < 4; rr++) {
                float4 cv = *(const float4*)&ctC[(mq * 4 + rr) * Kd + k];
                acc[rr] += cv.x * wv.x + cv.y * wv.y + cv.z * wv.z + cv.w * wv.w;
            }
        }
        #pragma unroll
        for (int rr = 0; rr < 4; rr++)
            WhS[(ch * 64 + mq * 4 + rr) * 65 + g] = acc[rr];
    }
    __syncthreads();
    if (tid < 256) {
        float s1 = 0.f, s2 = 0.f;
        #pragma unroll
        for (int c = 0; c < 64; c++) {
            float w = WhS[tid * 65 + c];
            s1 += w * aS[c];
            s2 += w * aS[64 + c];
        }
        f1[tid] = s1; f2[tid] = s2;
        e1[tid] = __expf(s1); e1p[tid] = __expf(0.2f * s1);
        e2[tid] = __expf(s2); e2p[tid] = __expf(0.2f * s2);
    }
    __syncthreads();

    int w = tid >> 5, lane = tid & 31;
    {
        int m = mBase + w;
        const float* adjrow = adj + (size_t)m * 256;
        float f1m = f1[m], E1m = e1[m], E1pm = e1p[m];
        float s = 0.f;
        for (int k = lane; k < 256; k += 32) {
            float f = f1m + f2[k];
            float p = (f >= 0.f) ? E1m * e2[k] : E1pm * e2p[k];
            p = (adjrow[k] > 0.f) ? p : 0.f;
            pb[w * 256 + k] = p;
            s += p;
        }
        #pragma unroll
        for (int o = 16; o; o >>= 1) s += __shfl_xor_sync(0xffffffffu, s, o);
        float inv = 1.f / s;
        __syncwarp();
        #pragma unroll
        for (int c0 = 0; c0 < 64; c0 += 32) {
            int c = c0 + lane;
            float acc0 = 0.f, acc1 = 0.f;
            for (int k = 0; k < 256; k += 4) {
                float4 p4 = *(const float4*)&pb[w * 256 + k];
                acc0 += p4.x * WhS[(k + 0) * 65 + c] + p4.z * WhS[(k + 2) * 65 + c];
                acc1 += p4.y * WhS[(k + 1) * 65 + c] + p4.w * WhS[(k + 3) * 65 + c];
            }
            outp[(size_t)m * outRowStride + dstOff + c] = (acc0 + acc1) * inv;
        }
    }
}

// ---------------- launch -------------------------------------------------------
extern "C" void kernel_launch(void* const* d_in, const int* in_sizes, int n_in,
                              void* d_out, int out_size)
{
    const float* x     = (const float*)d_in[0];
    const float* Fadj  = (const float*)d_in[1];
    const float* Tadj  = (const float*)d_in[2];
    const float* adj   = (const float*)d_in[3];
    const float* Hpre  = (const float*)d_in[4];
    const float* FattW = (const float*)d_in[5];
    const float* Fatta = (const float*)d_in[6];
    const float* TattW = (const float*)d_in[7];
    const float* Tatta = (const float*)d_in[8];
    const float* Wih0  = (const float*)d_in[9];
    const float* Whh0  = (const float*)d_in[10];
    const float* bih0  = (const float*)d_in[11];
    const float* bhh0  = (const float*)d_in[12];
    const float* Wih1  = (const float*)d_in[13];
    const float* Whh1  = (const float*)d_in[14];
    const float* bih1  = (const float*)d_in[15];
    const float* bhh1  = (const float*)d_in[16];
    const float* fc1w  = (const float*)d_in[17];
    const float* fc1b  = (const float*)d_in[18];
    const float* fc2w  = (const float*)d_in[19];
    const float* fc2b  = (const float*)d_in[20];
    const float* fc3w  = (const float*)d_in[21];
    const float* fc3b  = (const float*)d_in[22];
    const float* oW    = (const float*)d_in[23];
    const float* oa    = (const float*)d_in[24];
    const float* o1W   = (const float*)d_in[25];
    const float* o1a   = (const float*)d_in[26];
    const float* o2W   = (const float*)d_in[27];
    const float* o2a   = (const float*)d_in[28];
    float* out = (float*)d_out;

    float *WhF, *WhT, *Tat, *Fat, *gi, *gru, *ct, *cat2, *Fb;
    cudaGetSymbolAddress((void**)&WhF,  g_WhF);
    cudaGetSymbolAddress((void**)&WhT,  g_WhT);
    cudaGetSymbolAddress((void**)&Tat,  g_Tat);
    cudaGetSymbolAddress((void**)&Fat,  g_Fat);
    cudaGetSymbolAddress((void**)&gi,   g_gi);
    cudaGetSymbolAddress((void**)&gru,  g_gru);
    cudaGetSymbolAddress((void**)&ct,   g_ct);
    cudaGetSymbolAddress((void**)&cat2, g_cat2);
    cudaGetSymbolAddress((void**)&Fb,   g_F);
    float* F1F = Fb;
    float* F2F = Fb + NN * WWIN;
    float* F1T = Fb + 2 * NN * WWIN;
    float* F2T = Fb + 3 * NN * WWIN;

    cudaFuncSetAttribute(out_gat, cudaFuncAttributeMaxDynamicSharedMemorySize, 180224);

    // 1. zero f1/f2 accumulators
    cudaMemsetAsync(Fb, 0, 4 * NN * WWIN * sizeof(float));

    // 2. both Wh GEMMs (Feature + Time), compact grid
    gemm_wh_both<<<dim3(1, 1, 1024), 256>>>(x, FattW, Fatta, TattW, Tatta,
                                            WhF, WhT, F1F, F2F, F1T, F2T);

    // 3. both softmax+PV, compact grid, broadcast-A tiles
    gat_pv_both<<<dim3(1, 1, 1024), 256>>>(F1F, F2F, Fadj, WhF, Fat,
                                           F1T, F2T, Tadj, WhT, Tat);

    // 4. gi = [Fat | Tat^T | x] @ Wih0^T + bih0
    gi_gemm<<<256, 256>>>(Fat, Tat, x, Wih0, bih0, gi);

    // 5. GRU recurrence (cat_H -> d_out[16384:])
    gru_kernel<<<256, 64>>>(gi, Whh0, bhh0, Wih1, bih1, Whh1, bhh1, Hpre,
                            gru, out + 16384);

    // 6. FC stack -> ct
    fc_fused<<<256, 256>>>(gru, fc1w, fc1b, fc2w, fc2b, fc3w, fc3b, ct);

    // 7. output GATs out/out1 -> cat2
    {
        size_t smem = (256*65 + 64*68 + 64*64 + 128 + 6*256 + 32*256) * sizeof(float);
        out_gat<<<dim3(8, 2), 1024, smem>>>(ct, 64, 64, oW, oa, o1W, o1a,
                                            adj, cat2, 128);
    }
    // 8. final GAT -> d_out[0:16384]
    {
        size_t smem = (256*65 + 64*132 + 64*128 + 128 + 6*256 + 32*256) * sizeof(float);
        out_gat<<<dim3(8, 1), 1024, smem>>>(cat2, 128, 128, o2W, o2a, o2W, o2a,
                                            adj, out, 64);
    }
}